// round 14
// baseline (speedup 1.0000x reference)
#include <cuda_runtime.h>
#include <cuda_bf16.h>
#include <math.h>
#include <stdint.h>

#define T_STEPS 128
#define B_ENV   128
#define HID     512
#define TBTOT   (T_STEPS * B_ENV)
#define ZD      8
#define AD      7
#define FE      128
#define NB_LSTM 128

// ----------------------------------------------------------------------------
// Scratch (device globals; no allocation allowed)
// ----------------------------------------------------------------------------
__device__ __nv_bfloat16 g_a1h[TBTOT * 4096];
__device__ __nv_bfloat16 g_a1l[TBTOT * 4096];
__device__ __nv_bfloat16 g_h1h[TBTOT * HID];
__device__ __nv_bfloat16 g_h1l[TBTOT * HID];
__device__ __nv_bfloat16 g_h2h[TBTOT * HID];
__device__ __nv_bfloat16 g_h2l[TBTOT * HID];
__device__ float g_xg[TBTOT * 2048];
__device__ __nv_bfloat16 g_feath[TBTOT * HID];
__device__ __nv_bfloat16 g_featl[TBTOT * HID];
__device__ float g_lf[TBTOT * FE];
__device__ float g_cst[B_ENV * HID];
__device__ __nv_bfloat16 g_hhA[B_ENV * HID];
__device__ __nv_bfloat16 g_hlA[B_ENV * HID];
__device__ __nv_bfloat16 g_hhB[B_ENV * HID];
__device__ __nv_bfloat16 g_hlB[B_ENV * HID];
__device__ __nv_bfloat16 g_wlh[128 * 16 * 512];
__device__ __nv_bfloat16 g_wll[128 * 16 * 512];
__device__ __nv_bfloat16 g_wfc1_hi[512 * 4096];
__device__ __nv_bfloat16 g_wfc1_lo[512 * 4096];
__device__ __nv_bfloat16 g_wfc2_hi[512 * 512];
__device__ __nv_bfloat16 g_wfc2_lo[512 * 512];
__device__ __nv_bfloat16 g_wih_hi[2048 * 512];
__device__ __nv_bfloat16 g_wih_lo[2048 * 512];
__device__ __nv_bfloat16 g_wlf_hi[128 * 512];
__device__ __nv_bfloat16 g_wlf_lo[128 * 512];
__device__ __nv_bfloat16 g_cw1h[25 * 256];
__device__ __nv_bfloat16 g_cw1l[25 * 256];
__device__ __nv_bfloat16 g_cw2h[9 * 256];
__device__ __nv_bfloat16 g_cw2l[9 * 256];
__device__ __nv_bfloat16 g_cw3h[9 * 256];
__device__ __nv_bfloat16 g_cw3l[9 * 256];
// flag-array grid barrier (monotonic per-block counters; zero-init)
__device__ volatile unsigned int g_flags[NB_LSTM];

// ============================================================================
// Helpers
// ============================================================================
__device__ __forceinline__ uint32_t smem_to_u32(const void* smem_ptr) {
    uint32_t addr;
    asm("{ .reg .u64 tmp; cvta.to.shared.u64 tmp, %1; cvt.u32.u64 %0, tmp; }"
        : "=r"(addr) : "l"(smem_ptr));
    return addr;
}

__device__ __forceinline__ void ldsm4(uint32_t addr, uint32_t* r) {
    asm volatile("ldmatrix.sync.aligned.m8n8.x4.shared.b16 {%0,%1,%2,%3}, [%4];"
        : "=r"(r[0]), "=r"(r[1]), "=r"(r[2]), "=r"(r[3]) : "r"(addr));
}

__device__ __forceinline__ void mma16816(float* d, const uint32_t* a,
                                         const uint32_t* b) {
    asm volatile(
        "mma.sync.aligned.m16n8k16.row.col.f32.bf16.bf16.f32 "
        "{%0,%1,%2,%3}, {%4,%5,%6,%7}, {%8,%9}, {%0,%1,%2,%3};"
        : "+f"(d[0]), "+f"(d[1]), "+f"(d[2]), "+f"(d[3])
        : "r"(a[0]), "r"(a[1]), "r"(a[2]), "r"(a[3]), "r"(b[0]), "r"(b[1]));
}

__device__ __forceinline__ void split2(float x, float y, uint32_t& hi, uint32_t& lo) {
    __nv_bfloat16 hx = __float2bfloat16(x), hy = __float2bfloat16(y);
    __nv_bfloat162 h2; h2.x = hx; h2.y = hy;
    hi = reinterpret_cast<uint32_t&>(h2);
    float lx = x - __bfloat162float(hx);
    float ly = y - __bfloat162float(hy);
    __nv_bfloat162 l2 = __floats2bfloat162_rn(lx, ly);
    lo = reinterpret_cast<uint32_t&>(l2);
}

#define CP_ASYNC16(dst, src) \
    asm volatile("cp.async.ca.shared.global [%0], [%1], 16;" \
        :: "r"(dst), "l"(src) : "memory")
#define CP_COMMIT() asm volatile("cp.async.commit_group;" ::: "memory")
#define CP_WAIT2() asm volatile("cp.async.wait_group 2;" ::: "memory")

// ----------------------------------------------------------------------------
// Weight prep kernels
// ----------------------------------------------------------------------------
__global__ void wprep(const float* __restrict__ w, __nv_bfloat16* __restrict__ hi,
                      __nv_bfloat16* __restrict__ lo, int total4) {
    int idx = blockIdx.x * blockDim.x + threadIdx.x;
    if (idx >= total4) return;
    float4 a = *(const float4*)(w + (size_t)idx * 4);
    uint32_t h0, h1, l0, l1;
    split2(a.x, a.y, h0, l0);
    split2(a.z, a.w, h1, l1);
    *(uint2*)(hi + (size_t)idx * 4) = make_uint2(h0, h1);
    *(uint2*)(lo + (size_t)idx * 4) = make_uint2(l0, l1);
}

__global__ void wprep_ld(const float* __restrict__ w, __nv_bfloat16* __restrict__ hi,
                         __nv_bfloat16* __restrict__ lo, int rows, int ldw) {
    int idx = blockIdx.x * blockDim.x + threadIdx.x;
    if (idx >= rows * 128) return;
    int row = idx >> 7;
    int k4 = (idx & 127) * 4;
    float4 a = *(const float4*)(w + (size_t)row * ldw + k4);
    uint32_t h0, h1, l0, l1;
    split2(a.x, a.y, h0, l0);
    split2(a.z, a.w, h1, l1);
    *(uint2*)(hi + (size_t)row * 512 + k4) = make_uint2(h0, h1);
    *(uint2*)(lo + (size_t)row * 512 + k4) = make_uint2(l0, l1);
}

__global__ void wcprep_all(const float* __restrict__ w1, const float* __restrict__ w2,
                           const float* __restrict__ w3) {
    int idx = blockIdx.x * blockDim.x + threadIdx.x;
    const float* w;
    __nv_bfloat16 *hi, *lo;
    int taps, local;
    if (idx < 6400) { w = w1; hi = g_cw1h; lo = g_cw1l; taps = 25; local = idx; }
    else if (idx < 8704) { w = w2; hi = g_cw2h; lo = g_cw2l; taps = 9; local = idx - 6400; }
    else if (idx < 11008) { w = w3; hi = g_cw3h; lo = g_cw3l; taps = 9; local = idx - 8704; }
    else return;
    int r = local & 255;
    int t = local >> 8;
    float v = w[r * taps + t];
    __nv_bfloat16 hv = __float2bfloat16(v);
    hi[t * 256 + r] = hv;
    lo[t * 256 + r] = __float2bfloat16(v - __bfloat162float(hv));
}

__global__ void wlstm_prep(const float* __restrict__ whh) {
    int idx = blockIdx.x * blockDim.x + threadIdx.x;
    if (idx >= 2048 * 128) return;
    int row = idx >> 7;
    int k4 = (idx & 127) * 4;
    int g = row >> 9, j = row & 511;
    int blk = j >> 2, jj = j & 3;
    int n = 2 * jj + (g & 1) + 8 * (g >> 1);
    size_t dst = ((size_t)(blk * 16 + n)) * 512 + k4;
    float4 v = *(const float4*)(whh + (size_t)row * 512 + k4);
    uint32_t h0, h1, l0, l1;
    split2(v.x, v.y, h0, l0);
    split2(v.z, v.w, h1, l1);
    *(uint2*)(g_wlh + dst) = make_uint2(h0, h1);
    *(uint2*)(g_wll + dst) = make_uint2(l0, l1);
}

// pack h0 pre-masked + copy c0 (merged)
__global__ void pack_hc0(const float* __restrict__ h0, const float* __restrict__ c0,
                         const int* __restrict__ done) {
    int i = blockIdx.x * blockDim.x + threadIdx.x;
    if (i >= B_ENV * HID) return;
    int b = i >> 9;
    float m = done[b] ? 0.f : 1.f;
    float v = h0[i] * m;
    __nv_bfloat16 hv = __float2bfloat16(v);
    g_hhA[i] = hv;
    g_hlA[i] = __float2bfloat16(v - __bfloat162float(hv));
    g_cst[i] = c0[i];
}

// ----------------------------------------------------------------------------
// tgemm2 (proven): pre-split operands, cp.async depth-3 pipeline
// ----------------------------------------------------------------------------
#define SMSTR 80
#define TG_BUF 40960
#define TG_SMEM (4 * TG_BUF)

template <int ACT, int OUTSPLIT, int ZMODE>
__global__ __launch_bounds__(256) void tgemm2(
    const __nv_bfloat16* __restrict__ Ahi, const __nv_bfloat16* __restrict__ Alo,
    const __nv_bfloat16* __restrict__ Whi, const __nv_bfloat16* __restrict__ Wlo,
    const float* __restrict__ bias, const float* __restrict__ bias2,
    float* __restrict__ C, __nv_bfloat16* __restrict__ Chi,
    __nv_bfloat16* __restrict__ Clo,
    const float* __restrict__ Wzf, int ldw, const int* __restrict__ z,
    int M, int N, int K) {
    extern __shared__ uint8_t sm[];
    uint32_t sb = smem_to_u32(sm);
    int tid = threadIdx.x;
    int lane = tid & 31;
    int wid = tid >> 5;
    int wm = wid & 3, wn = wid >> 2;
    int m0 = blockIdx.y * 128, n0 = blockIdx.x * 128;
    int sr0 = tid >> 2, sq = tid & 3;
    int nslab = K / 32;

    float acc[2][8][4];
#pragma unroll
    for (int i = 0; i < 2; i++)
#pragma unroll
        for (int j = 0; j < 8; j++)
#pragma unroll
            for (int q = 0; q < 4; q++) acc[i][j][q] = 0.f;

    auto cpa = [&](int s) {
        uint32_t buf = sb + (uint32_t)((s & 3) * TG_BUF);
        size_t ko = (size_t)s * 32 + sq * 8;
#pragma unroll
        for (int q = 0; q < 2; q++) {
            int r = sr0 + 64 * q;
            uint32_t d = (uint32_t)(r * SMSTR + sq * 16);
            CP_ASYNC16(buf + d,         Ahi + (size_t)(m0 + r) * K + ko);
            CP_ASYNC16(buf + 10240 + d, Alo + (size_t)(m0 + r) * K + ko);
            CP_ASYNC16(buf + 20480 + d, Whi + (size_t)(n0 + r) * K + ko);
            CP_ASYNC16(buf + 30720 + d, Wlo + (size_t)(n0 + r) * K + ko);
        }
        CP_COMMIT();
    };

    cpa(0); cpa(1); cpa(2);

    int g = lane >> 3;
    int arow_off = (lane & 7) + (g & 1) * 8;
    int akb_off = (g >> 1) * 16;
    int brow_off = (lane & 7) + (g >> 1) * 8;
    int bkb_off = (g & 1) * 16;

    for (int s = 0; s < nslab; s++) {
        CP_WAIT2();
        __syncthreads();
        if (s + 3 < nslab) cpa(s + 3);
        else CP_COMMIT();
        uint32_t buf = sb + (uint32_t)((s & 3) * TG_BUF);
#pragma unroll
        for (int kk2 = 0; kk2 < 2; kk2++) {
            int kb = kk2 * 32;
            uint32_t ah[2][4], al[2][4], bh[4][4], bl[4][4];
#pragma unroll
            for (int mi = 0; mi < 2; mi++) {
                uint32_t r = (uint32_t)((wm * 32 + mi * 16 + arow_off) * SMSTR +
                                        kb + akb_off);
                ldsm4(buf + r, ah[mi]);
                ldsm4(buf + 10240 + r, al[mi]);
            }
#pragma unroll
            for (int pi = 0; pi < 4; pi++) {
                uint32_t r = (uint32_t)((wn * 64 + pi * 16 + brow_off) * SMSTR +
                                        kb + bkb_off);
                ldsm4(buf + 20480 + r, bh[pi]);
                ldsm4(buf + 30720 + r, bl[pi]);
            }
#pragma unroll
            for (int mi = 0; mi < 2; mi++)
#pragma unroll
                for (int pi = 0; pi < 4; pi++)
#pragma unroll
                    for (int half = 0; half < 2; half++) {
                        float* d = acc[mi][pi * 2 + half];
                        mma16816(d, ah[mi], &bh[pi][half * 2]);
                        mma16816(d, ah[mi], &bl[pi][half * 2]);
                        mma16816(d, al[mi], &bh[pi][half * 2]);
                    }
        }
    }
    __syncthreads();

    float* ct = (float*)sm;
#pragma unroll
    for (int mi = 0; mi < 2; mi++) {
        int r0 = wm * 32 + mi * 16 + (lane >> 2);
        int z0 = 0, z1 = 0;
        if (ZMODE) {
            z0 = z[m0 + r0];
            z1 = z[m0 + r0 + 8];
        }
#pragma unroll
        for (int ni = 0; ni < 8; ni++) {
            int c = wn * 64 + ni * 8 + (lane & 3) * 2;
            float b0 = bias[n0 + c], b1 = bias[n0 + c + 1];
            if (bias2) { b0 += bias2[n0 + c]; b1 += bias2[n0 + c + 1]; }
            float v0 = acc[mi][ni][0] + b0;
            float v1 = acc[mi][ni][1] + b1;
            float v2 = acc[mi][ni][2] + b0;
            float v3 = acc[mi][ni][3] + b1;
            if (ZMODE) {
                v0 += Wzf[(size_t)(n0 + c) * ldw + 512 + z0];
                v1 += Wzf[(size_t)(n0 + c + 1) * ldw + 512 + z0];
                v2 += Wzf[(size_t)(n0 + c) * ldw + 512 + z1];
                v3 += Wzf[(size_t)(n0 + c + 1) * ldw + 512 + z1];
            }
            if (ACT) {
                v0 = v0 > 0.f ? v0 : 0.01f * v0;
                v1 = v1 > 0.f ? v1 : 0.01f * v1;
                v2 = v2 > 0.f ? v2 : 0.01f * v2;
                v3 = v3 > 0.f ? v3 : 0.01f * v3;
            }
            ct[r0 * 132 + c] = v0;
            ct[r0 * 132 + c + 1] = v1;
            ct[(r0 + 8) * 132 + c] = v2;
            ct[(r0 + 8) * 132 + c + 1] = v3;
        }
    }
    __syncthreads();
    {
        int r8 = tid >> 5;
        int c4 = (tid & 31) * 4;
#pragma unroll
        for (int p = 0; p < 16; p++) {
            int r = p * 8 + r8;
            float4 v = *(const float4*)(ct + r * 132 + c4);
            size_t o = (size_t)(m0 + r) * N + n0 + c4;
            if (OUTSPLIT) {
                uint32_t h0, h1, l0, l1;
                split2(v.x, v.y, h0, l0);
                split2(v.z, v.w, h1, l1);
                *(uint2*)(Chi + o) = make_uint2(h0, h1);
                *(uint2*)(Clo + o) = make_uint2(l0, l1);
            } else {
                *(float4*)(C + o) = v;
            }
        }
    }
}

// ----------------------------------------------------------------------------
// HMMA conv (proven); final layer writes SPLIT bf16 activations
// ----------------------------------------------------------------------------
#define PSTR 48
#define IMG_BYTES (400 * PSTR)
#define CW_OFF   (2 * IMG_BYTES)
#define CW_HALF  12800

template <int KS, int P, int LAST>
__device__ __forceinline__ void conv_hmma_layer(
    uint8_t* csm, uint32_t sbase, const __nv_bfloat16* wsrc_h,
    const __nv_bfloat16* wsrc_l, const float* __restrict__ bias,
    __nv_bfloat16* goh, __nv_bfloat16* gol, int tid, int lane, int wid) {
    const int taps = KS * KS;
    {
        const uint4* sh = (const uint4*)wsrc_h;
        const uint4* sl = (const uint4*)wsrc_l;
        uint4* dh = (uint4*)(csm + CW_OFF);
        uint4* dl = (uint4*)(csm + CW_OFF + CW_HALF);
        for (int i = tid; i < taps * 32; i += 256) {
            dh[i] = sh[i];
            dl[i] = sl[i];
        }
    }
    __syncthreads();

    float acc[2][2][4];
#pragma unroll
    for (int a = 0; a < 2; a++)
#pragma unroll
        for (int b = 0; b < 2; b++)
#pragma unroll
            for (int q = 0; q < 4; q++) acc[a][b][q] = 0.f;

    int g = lane >> 3;
    int h0 = wid * 2;
    uint32_t aoff[2];
#pragma unroll
    for (int mi = 0; mi < 2; mi++)
        aoff[mi] = (uint32_t)(((h0 + mi + 2) * 20 + 2 + (lane & 7) + (g & 1) * 8) * PSTR +
                              (g >> 1) * 16);
    uint32_t boff = (uint32_t)(((lane & 7) + (g >> 1) * 8) * 32 + (g & 1) * 16);
    uint32_t wb_h = sbase + CW_OFF;
    uint32_t wb_l = sbase + CW_OFF + CW_HALF;

#pragma unroll
    for (int kh = 0; kh < KS; kh++) {
#pragma unroll
        for (int kw = 0; kw < KS; kw++) {
            int t = kh * KS + kw;
            int shift = ((kh - P) * 20 + (kw - P)) * PSTR;
            uint32_t bh4[4], bl4[4];
            ldsm4(wb_h + t * 512 + boff, bh4);
            ldsm4(wb_l + t * 512 + boff, bl4);
#pragma unroll
            for (int mi = 0; mi < 2; mi++) {
                uint32_t ah[4], al[4];
                ldsm4(sbase + aoff[mi] + shift, ah);
                ldsm4(sbase + IMG_BYTES + aoff[mi] + shift, al);
#pragma unroll
                for (int nh = 0; nh < 2; nh++) {
                    mma16816(acc[mi][nh], ah, &bh4[nh * 2]);
                    mma16816(acc[mi][nh], ah, &bl4[nh * 2]);
                    mma16816(acc[mi][nh], al, &bh4[nh * 2]);
                }
            }
        }
    }
    __syncthreads();

#pragma unroll
    for (int mi = 0; mi < 2; mi++) {
        int h = h0 + mi;
#pragma unroll
        for (int nh = 0; nh < 2; nh++) {
            int co = nh * 8 + (lane & 3) * 2;
            float b0 = bias[co], b1 = bias[co + 1];
#pragma unroll
            for (int rr = 0; rr < 2; rr++) {
                int w = (lane >> 2) + rr * 8;
                float v0 = acc[mi][nh][rr * 2 + 0] + b0;
                float v1 = acc[mi][nh][rr * 2 + 1] + b1;
                v0 = v0 > 0.f ? v0 : 0.01f * v0;
                v1 = v1 > 0.f ? v1 : 0.01f * v1;
                if (LAST) {
                    int k0 = co * 256 + h * 16 + w;
                    __nv_bfloat16 hv0 = __float2bfloat16(v0);
                    goh[k0] = hv0;
                    gol[k0] = __float2bfloat16(v0 - __bfloat162float(hv0));
                    __nv_bfloat16 hv1 = __float2bfloat16(v1);
                    goh[k0 + 256] = hv1;
                    gol[k0 + 256] = __float2bfloat16(v1 - __bfloat162float(hv1));
                } else {
                    uint32_t hp, lp;
                    split2(v0, v1, hp, lp);
                    int pb = ((h + 2) * 20 + (w + 2)) * PSTR + co * 2;
                    *(uint32_t*)(csm + pb) = hp;
                    *(uint32_t*)(csm + IMG_BYTES + pb) = lp;
                }
            }
        }
    }
    __syncthreads();
}

__global__ __launch_bounds__(256) void conv3_mma(
    const float* __restrict__ x,
    const float* __restrict__ b1, const float* __restrict__ b2,
    const float* __restrict__ b3) {
    extern __shared__ uint8_t csm[];
    uint32_t sbase = smem_to_u32(csm);
    int tid = threadIdx.x;
    int lane = tid & 31;
    int wid = tid >> 5;
    int img = blockIdx.x;
    const float* xi = x + (size_t)img * 4096;

    for (int i = tid; i < 2 * IMG_BYTES / 4; i += 256)
        ((uint32_t*)csm)[i] = 0;
    __syncthreads();
    for (int i = tid; i < 4096; i += 256) {
        int ci = i >> 8, p = i & 255;
        int h = p >> 4, w = p & 15;
        float v = xi[i];
        __nv_bfloat16 hv = __float2bfloat16(v);
        float lv = v - __bfloat162float(hv);
        int pb = ((h + 2) * 20 + (w + 2)) * PSTR + ci * 2;
        *(__nv_bfloat16*)(csm + pb) = hv;
        *(__nv_bfloat16*)(csm + IMG_BYTES + pb) = __float2bfloat16(lv);
    }
    __syncthreads();

    __nv_bfloat16* goh = g_a1h + (size_t)img * 4096;
    __nv_bfloat16* gol = g_a1l + (size_t)img * 4096;
    conv_hmma_layer<5, 2, 0>(csm, sbase, g_cw1h, g_cw1l, b1, goh, gol, tid, lane, wid);
    conv_hmma_layer<3, 1, 0>(csm, sbase, g_cw2h, g_cw2l, b2, goh, gol, tid, lane, wid);
    conv_hmma_layer<3, 1, 1>(csm, sbase, g_cw3h, g_cw3l, b3, goh, gol, tid, lane, wid);
}

// ----------------------------------------------------------------------------
// Persistent LSTM v6: 64-k slabs, cp.async depth-3; flag-array grid barrier.
// ----------------------------------------------------------------------------
__device__ __forceinline__ float sigm(float x) { return 1.f / (1.f + expf(-x)); }

#define LW_STR   1040
#define LA_STR   144
#define LS_W_SZ  (2 * 16 * LW_STR)
#define LS_A_OFF LS_W_SZ
#define LS_A_BUF (2 * 128 * LA_STR)
#define LS_M_OFF (LS_A_OFF + 4 * LS_A_BUF)
#define LS_SMEM  (LS_M_OFF + 1024)

__global__ __launch_bounds__(256) void lstm_persist(
    const float* __restrict__ xg, const int* __restrict__ done,
    __nv_bfloat16* __restrict__ hAh, __nv_bfloat16* __restrict__ hAl,
    __nv_bfloat16* __restrict__ hBh, __nv_bfloat16* __restrict__ hBl,
    float* __restrict__ c_st) {
    extern __shared__ uint8_t psm[];
    float* s_m  = (float*)(psm + LS_M_OFF);
    float* s_mn = (float*)(psm + LS_M_OFF + 512);
    uint32_t sbW = smem_to_u32(psm);
    int tid = threadIdx.x, lane = tid & 31, wid = tid >> 5;
    int blk = blockIdx.x;
    int jb4 = blk * 4;

    // barrier generation base (flags persist across graph replays; all equal)
    unsigned int bar_base = g_flags[blk];

    {
        const uint4* Wh = (const uint4*)(g_wlh + (size_t)blk * 16 * 512);
        const uint4* Wl = (const uint4*)(g_wll + (size_t)blk * 16 * 512);
#pragma unroll
        for (int i = 0; i < 4; i++) {
            int i4 = tid + 256 * i;
            int r = i4 >> 6, q = i4 & 63;
            *(uint4*)(psm + r * LW_STR + q * 16) = Wh[i4];
            *(uint4*)(psm + 16 * LW_STR + r * LW_STR + q * 16) = Wl[i4];
        }
    }

    int r1 = wid * 16 + (lane >> 2);
    int L = lane & 3;
    int gq = lane >> 3;
    uint32_t arow = (uint32_t)((wid * 16 + (lane & 7) + (gq & 1) * 8) * LA_STR +
                               (gq >> 1) * 16);
    uint32_t brow = (uint32_t)(((lane & 7) + (gq >> 1) * 8) * LW_STR + (gq & 1) * 16);

    float creg[2];
#pragma unroll
    for (int rr = 0; rr < 2; rr++)
        creg[rr] = c_st[(size_t)(r1 + rr * 8) * 512 + jb4 + L];
    __syncthreads();

    for (int t = 0; t < T_STEPS; t++) {
        const __nv_bfloat16* hih = (t & 1) ? hBh : hAh;
        const __nv_bfloat16* hil = (t & 1) ? hBl : hAl;
        __nv_bfloat16* hoh = (t & 1) ? hAh : hBh;
        __nv_bfloat16* hol = (t & 1) ? hAl : hBl;

        auto cpa_slab = [&](int s) {
            uint32_t base = sbW + LS_A_OFF + (uint32_t)((s & 3) * LS_A_BUF);
#pragma unroll
            for (int i = 0; i < 4; i++) {
                int idx = tid + 256 * i;
                int r = idx >> 3, ch = idx & 7;
                CP_ASYNC16(base + r * LA_STR + ch * 16,
                           hih + (size_t)r * 512 + s * 64 + ch * 8);
                CP_ASYNC16(base + 128 * LA_STR + r * LA_STR + ch * 16,
                           hil + (size_t)r * 512 + s * 64 + ch * 8);
            }
            CP_COMMIT();
        };

        cpa_slab(0);
        cpa_slab(1);
        cpa_slab(2);

        if (tid < 128) {
            s_m[tid] = done[t * 128 + tid] ? 0.f : 1.f;
            s_mn[tid] = (t + 1 < T_STEPS)
                            ? (done[(t + 1) * 128 + tid] ? 0.f : 1.f) : 1.f;
        }

        float acc[2][4];
#pragma unroll
        for (int pi = 0; pi < 2; pi++)
#pragma unroll
            for (int rr = 0; rr < 2; rr++)
#pragma unroll
                for (int cc = 0; cc < 2; cc++)
                    acc[pi][rr * 2 + cc] = xg[(size_t)(t * 128 + r1 + rr * 8) * 2048 +
                                              (cc + 2 * pi) * 512 + jb4 + L];

        for (int s = 0; s < 8; s++) {
            CP_WAIT2();
            __syncthreads();
            if (s < 5) cpa_slab(s + 3);
            else CP_COMMIT();
            uint32_t sbA = sbW + LS_A_OFF + (uint32_t)((s & 3) * LS_A_BUF);
#pragma unroll
            for (int kk2 = 0; kk2 < 4; kk2++) {
                int kb = kk2 * 32;
                uint32_t ah[4], al[4], bh4[4], bl4[4];
                ldsm4(sbA + arow + kb, ah);
                ldsm4(sbA + 128 * LA_STR + arow + kb, al);
                uint32_t bo = brow + s * 128 + kb;
                ldsm4(sbW + bo, bh4);
                ldsm4(sbW + 16 * LW_STR + bo, bl4);
#pragma unroll
                for (int pi = 0; pi < 2; pi++) {
                    float* d = acc[pi];
                    mma16816(d, ah, &bh4[pi * 2]);
                    mma16816(d, ah, &bl4[pi * 2]);
                    mma16816(d, al, &bh4[pi * 2]);
                }
            }
        }

#pragma unroll
        for (int rr = 0; rr < 2; rr++) {
            int r = r1 + rr * 8;
            float m = s_m[r];
            float mn = s_mn[r];
            int j = jb4 + L;
            float gi = acc[0][rr * 2 + 0];
            float gf = acc[0][rr * 2 + 1];
            float gg = acc[1][rr * 2 + 0];
            float go = acc[1][rr * 2 + 1];
            float cn = sigm(gf) * (creg[rr] * m) + sigm(gi) * tanhf(gg);
            float hn = sigm(go) * tanhf(cn);
            creg[rr] = cn;
            size_t fo = (size_t)(t * 128 + r) * 512 + j;
            __nv_bfloat16 fh = __float2bfloat16(hn);
            g_feath[fo] = fh;
            g_featl[fo] = __float2bfloat16(hn - __bfloat162float(fh));
            float hw = hn * mn;
            __nv_bfloat16 hh = __float2bfloat16(hw);
            hoh[(size_t)r * 512 + j] = hh;
            hol[(size_t)r * 512 + j] = __float2bfloat16(hw - __bfloat162float(hh));
        }

        // flag-array grid barrier (skip after the last step)
        if (t + 1 < T_STEPS) {
            unsigned int gen = bar_base + (unsigned int)(t + 1);
            __threadfence();
            __syncthreads();
            if (tid == 0) g_flags[blk] = gen;
            if (tid < NB_LSTM) {
                while (g_flags[tid] < gen) { }
            }
            __threadfence();
            __syncthreads();
        } else {
            // still advance own flag so bar_base stays uniform next launch
            __syncthreads();
            if (tid == 0) g_flags[blk] = bar_base + (unsigned int)T_STEPS;
        }
    }
}

// ----------------------------------------------------------------------------
// Head: warp per row; actor/critic GEMV + log_softmax/entropy/prob pack.
// ----------------------------------------------------------------------------
__global__ __launch_bounds__(256) void head_kernel(
    const float* __restrict__ lf, const float* __restrict__ aw,
    const float* __restrict__ ab, const float* __restrict__ cw,
    const float* __restrict__ cb, const int* __restrict__ action,
    float* __restrict__ out) {
    int warp = (blockIdx.x * blockDim.x + threadIdx.x) >> 5;
    int lane = threadIdx.x & 31;
    if (warp >= TBTOT) return;
    float4 f = *(const float4*)(lf + (size_t)warp * FE + lane * 4);
    float r[8];
#pragma unroll
    for (int a = 0; a < 7; a++) {
        float4 w = *(const float4*)(aw + a * FE + lane * 4);
        r[a] = f.x * w.x + f.y * w.y + f.z * w.z + f.w * w.w;
    }
    {
        float4 w = *(const float4*)(cw + lane * 4);
        r[7] = f.x * w.x + f.y * w.y + f.z * w.z + f.w * w.w;
    }
#pragma unroll
    for (int a = 0; a < 8; a++)
#pragma unroll
        for (int s = 16; s > 0; s >>= 1)
            r[a] += __shfl_xor_sync(0xffffffffu, r[a], s);

    if (lane == 0) {
        float lg[7];
        float mx = -1e30f;
#pragma unroll
        for (int a = 0; a < 7; a++) {
            lg[a] = r[a] + ab[a];
            mx = fmaxf(mx, lg[a]);
        }
        float se = 0.f;
        float e[7];
#pragma unroll
        for (int a = 0; a < 7; a++) {
            e[a] = expf(lg[a] - mx);
            se += e[a];
        }
        float lse = mx + logf(se);
        float inv = 1.f / se;
        float ent = 0.f;
        float* o = out + (size_t)warp * 10;
#pragma unroll
        for (int a = 0; a < 7; a++) {
            float p = e[a] * inv;
            float lp = lg[a] - lse;
            ent -= p * lp;
            o[3 + a] = p;
        }
        int act = action[warp];
        o[0] = lg[act] - lse;
        o[1] = ent;
        o[2] = r[7] + cb[0];
    }
}

// ----------------------------------------------------------------------------
// Launch (fork-join second stream overlaps preps with conv)
// ----------------------------------------------------------------------------
extern "C" void kernel_launch(void* const* d_in, const int* in_sizes, int n_in,
                              void* d_out, int out_size) {
    const float* x    = (const float*)d_in[0];
    const int* done   = (const int*)d_in[1];
    const int* z      = (const int*)d_in[2];
    const int* action = (const int*)d_in[3];
    const float* h0   = (const float*)d_in[4];
    const float* c0   = (const float*)d_in[5];
    const float* c1w = (const float*)d_in[6];  const float* c1b = (const float*)d_in[7];
    const float* c2w = (const float*)d_in[8];  const float* c2b = (const float*)d_in[9];
    const float* c3w = (const float*)d_in[10]; const float* c3b = (const float*)d_in[11];
    const float* fc1w = (const float*)d_in[12]; const float* fc1b = (const float*)d_in[13];
    const float* fc2w = (const float*)d_in[14]; const float* fc2b = (const float*)d_in[15];
    const float* wih = (const float*)d_in[16]; const float* whh = (const float*)d_in[17];
    const float* bih = (const float*)d_in[18]; const float* bhh = (const float*)d_in[19];
    const float* lfw = (const float*)d_in[20]; const float* lfb = (const float*)d_in[21];
    const float* aw = (const float*)d_in[22];  const float* ab = (const float*)d_in[23];
    const float* cw = (const float*)d_in[24];  const float* cb = (const float*)d_in[25];
    float* out = (float*)d_out;

    float *pxg, *plf, *pcst;
    __nv_bfloat16 *pa1h, *pa1l, *ph1h, *ph1l, *ph2h, *ph2l, *pfh, *pfl;
    __nv_bfloat16 *pw1h, *pw1l, *pw2h, *pw2l, *pwih_h, *pwih_l, *pwlfh, *pwlfl;
    __nv_bfloat16 *phhA, *phlA, *phhB, *phlB;
    cudaGetSymbolAddress((void**)&pa1h, g_a1h);
    cudaGetSymbolAddress((void**)&pa1l, g_a1l);
    cudaGetSymbolAddress((void**)&ph1h, g_h1h);
    cudaGetSymbolAddress((void**)&ph1l, g_h1l);
    cudaGetSymbolAddress((void**)&ph2h, g_h2h);
    cudaGetSymbolAddress((void**)&ph2l, g_h2l);
    cudaGetSymbolAddress((void**)&pxg, g_xg);
    cudaGetSymbolAddress((void**)&pfh, g_feath);
    cudaGetSymbolAddress((void**)&pfl, g_featl);
    cudaGetSymbolAddress((void**)&plf, g_lf);
    cudaGetSymbolAddress((void**)&pcst, g_cst);
    cudaGetSymbolAddress((void**)&phhA, g_hhA);
    cudaGetSymbolAddress((void**)&phlA, g_hlA);
    cudaGetSymbolAddress((void**)&phhB, g_hhB);
    cudaGetSymbolAddress((void**)&phlB, g_hlB);
    cudaGetSymbolAddress((void**)&pw1h, g_wfc1_hi);
    cudaGetSymbolAddress((void**)&pw1l, g_wfc1_lo);
    cudaGetSymbolAddress((void**)&pw2h, g_wfc2_hi);
    cudaGetSymbolAddress((void**)&pw2l, g_wfc2_lo);
    cudaGetSymbolAddress((void**)&pwih_h, g_wih_hi);
    cudaGetSymbolAddress((void**)&pwih_l, g_wih_lo);
    cudaGetSymbolAddress((void**)&pwlfh, g_wlf_hi);
    cudaGetSymbolAddress((void**)&pwlfl, g_wlf_lo);

    cudaFuncSetAttribute(tgemm2<1, 1, 0>, cudaFuncAttributeMaxDynamicSharedMemorySize, TG_SMEM);
    cudaFuncSetAttribute(tgemm2<0, 0, 0>, cudaFuncAttributeMaxDynamicSharedMemorySize, TG_SMEM);
    cudaFuncSetAttribute(tgemm2<1, 0, 1>, cudaFuncAttributeMaxDynamicSharedMemorySize, TG_SMEM);
    const int SMEM_CONV = 2 * IMG_BYTES + 2 * CW_HALF;
    cudaFuncSetAttribute(conv3_mma, cudaFuncAttributeMaxDynamicSharedMemorySize, SMEM_CONV);
    cudaFuncSetAttribute(lstm_persist, cudaFuncAttributeMaxDynamicSharedMemorySize, LS_SMEM);

    // lazily created side stream + events (created outside graph capture;
    // identical work on every call)
    static cudaStream_t s2 = nullptr;
    static cudaEvent_t evF = nullptr, evJ = nullptr;
    if (s2 == nullptr) {
        cudaStreamCreateWithFlags(&s2, cudaStreamNonBlocking);
        cudaEventCreateWithFlags(&evF, cudaEventDisableTiming);
        cudaEventCreateWithFlags(&evJ, cudaEventDisableTiming);
    }

    // conv weight prep must precede conv (stream 0)
    wcprep_all<<<(11008 + 255) / 256, 256>>>(c1w, c2w, c3w);

    // fork: all other preps run on s2, concurrent with conv
    cudaEventRecord(evF, 0);
    cudaStreamWaitEvent(s2, evF, 0);
    wprep<<<(512 * 1024 + 255) / 256, 256, 0, s2>>>(fc1w, pw1h, pw1l, 512 * 1024);
    wprep<<<(512 * 128 + 255) / 256, 256, 0, s2>>>(fc2w, pw2h, pw2l, 512 * 128);
    wprep<<<(2048 * 128 + 255) / 256, 256, 0, s2>>>(wih, pwih_h, pwih_l, 2048 * 128);
    wprep_ld<<<(128 * 128 + 255) / 256, 256, 0, s2>>>(lfw, pwlfh, pwlfl, 128, 520);
    wlstm_prep<<<(2048 * 128 + 255) / 256, 256, 0, s2>>>(whh);
    pack_hc0<<<(B_ENV * HID + 255) / 256, 256, 0, s2>>>(h0, c0, done);
    cudaEventRecord(evJ, s2);

    // conv on stream 0 (overlaps s2)
    conv3_mma<<<TBTOT, 256, SMEM_CONV>>>(x, c1b, c2b, c3b);

    // join before fc1 (fc1 needs pw1*, later kernels need the rest)
    cudaStreamWaitEvent(0, evJ, 0);

    tgemm2<1, 1, 0><<<dim3(4, 128), 256, TG_SMEM>>>(
        pa1h, pa1l, pw1h, pw1l, fc1b, nullptr,
        nullptr, ph1h, ph1l, nullptr, 0, nullptr, TBTOT, 512, 4096);
    tgemm2<1, 1, 0><<<dim3(4, 128), 256, TG_SMEM>>>(
        ph1h, ph1l, pw2h, pw2l, fc2b, nullptr,
        nullptr, ph2h, ph2l, nullptr, 0, nullptr, TBTOT, 512, 512);
    tgemm2<0, 0, 0><<<dim3(16, 128), 256, TG_SMEM>>>(
        ph2h, ph2l, pwih_h, pwih_l, bih, bhh,
        pxg, nullptr, nullptr, nullptr, 0, nullptr, TBTOT, 2048, 512);

    lstm_persist<<<NB_LSTM, 256, LS_SMEM>>>(pxg, done, phhA, phlA, phhB, phlB,
                                            pcst);

    tgemm2<1, 0, 1><<<dim3(1, 128), 256, TG_SMEM>>>(
        pfh, pfl, pwlfh, pwlfl, lfb, nullptr,
        plf, nullptr, nullptr, lfw, 520, z, TBTOT, FE, 512);

    head_kernel<<<TBTOT / 8, 256>>>(plf, aw, ab, cw, cb, action, out);
}

// round 15
// speedup vs baseline: 1.2629x; 1.2629x over previous
#include <cuda_runtime.h>
#include <cuda_bf16.h>
#include <math.h>
#include <stdint.h>

#define T_STEPS 128
#define B_ENV   128
#define HID     512
#define TBTOT   (T_STEPS * B_ENV)
#define ZD      8
#define AD      7
#define FE      128
#define NB_LSTM 128

// ----------------------------------------------------------------------------
// Scratch (device globals; no allocation allowed)
// ----------------------------------------------------------------------------
__device__ __nv_bfloat16 g_a1h[TBTOT * 4096];
__device__ __nv_bfloat16 g_a1l[TBTOT * 4096];
__device__ __nv_bfloat16 g_h1h[TBTOT * HID];
__device__ __nv_bfloat16 g_h1l[TBTOT * HID];
__device__ __nv_bfloat16 g_h2h[TBTOT * HID];
__device__ __nv_bfloat16 g_h2l[TBTOT * HID];
__device__ float g_xg[TBTOT * 2048];
__device__ __nv_bfloat16 g_feath[TBTOT * HID];
__device__ __nv_bfloat16 g_featl[TBTOT * HID];
__device__ float g_lf[TBTOT * FE];
__device__ float g_cst[B_ENV * HID];
__device__ __nv_bfloat16 g_hhA[B_ENV * HID];
__device__ __nv_bfloat16 g_hlA[B_ENV * HID];
__device__ __nv_bfloat16 g_hhB[B_ENV * HID];
__device__ __nv_bfloat16 g_hlB[B_ENV * HID];
__device__ __nv_bfloat16 g_wlh[128 * 16 * 512];
__device__ __nv_bfloat16 g_wll[128 * 16 * 512];
__device__ __nv_bfloat16 g_wfc1_hi[512 * 4096];
__device__ __nv_bfloat16 g_wfc1_lo[512 * 4096];
__device__ __nv_bfloat16 g_wfc2_hi[512 * 512];
__device__ __nv_bfloat16 g_wfc2_lo[512 * 512];
__device__ __nv_bfloat16 g_wih_hi[2048 * 512];
__device__ __nv_bfloat16 g_wih_lo[2048 * 512];
__device__ __nv_bfloat16 g_wlf_hi[128 * 512];
__device__ __nv_bfloat16 g_wlf_lo[128 * 512];
__device__ __nv_bfloat16 g_cw1h[25 * 256];
__device__ __nv_bfloat16 g_cw1l[25 * 256];
__device__ __nv_bfloat16 g_cw2h[9 * 256];
__device__ __nv_bfloat16 g_cw2l[9 * 256];
__device__ __nv_bfloat16 g_cw3h[9 * 256];
__device__ __nv_bfloat16 g_cw3l[9 * 256];
// grid barrier state (R13 proven: counting atomic + single-word generation)
__device__ unsigned int g_bar_cnt;
__device__ volatile unsigned int g_bar_gen;

// ============================================================================
// Helpers
// ============================================================================
__device__ __forceinline__ uint32_t smem_to_u32(const void* smem_ptr) {
    uint32_t addr;
    asm("{ .reg .u64 tmp; cvta.to.shared.u64 tmp, %1; cvt.u32.u64 %0, tmp; }"
        : "=r"(addr) : "l"(smem_ptr));
    return addr;
}

__device__ __forceinline__ void ldsm4(uint32_t addr, uint32_t* r) {
    asm volatile("ldmatrix.sync.aligned.m8n8.x4.shared.b16 {%0,%1,%2,%3}, [%4];"
        : "=r"(r[0]), "=r"(r[1]), "=r"(r[2]), "=r"(r[3]) : "r"(addr));
}

__device__ __forceinline__ void mma16816(float* d, const uint32_t* a,
                                         const uint32_t* b) {
    asm volatile(
        "mma.sync.aligned.m16n8k16.row.col.f32.bf16.bf16.f32 "
        "{%0,%1,%2,%3}, {%4,%5,%6,%7}, {%8,%9}, {%0,%1,%2,%3};"
        : "+f"(d[0]), "+f"(d[1]), "+f"(d[2]), "+f"(d[3])
        : "r"(a[0]), "r"(a[1]), "r"(a[2]), "r"(a[3]), "r"(b[0]), "r"(b[1]));
}

__device__ __forceinline__ void split2(float x, float y, uint32_t& hi, uint32_t& lo) {
    __nv_bfloat16 hx = __float2bfloat16(x), hy = __float2bfloat16(y);
    __nv_bfloat162 h2; h2.x = hx; h2.y = hy;
    hi = reinterpret_cast<uint32_t&>(h2);
    float lx = x - __bfloat162float(hx);
    float ly = y - __bfloat162float(hy);
    __nv_bfloat162 l2 = __floats2bfloat162_rn(lx, ly);
    lo = reinterpret_cast<uint32_t&>(l2);
}

#define CP_ASYNC16(dst, src) \
    asm volatile("cp.async.ca.shared.global [%0], [%1], 16;" \
        :: "r"(dst), "l"(src) : "memory")
#define CP_COMMIT() asm volatile("cp.async.commit_group;" ::: "memory")
#define CP_WAIT2() asm volatile("cp.async.wait_group 2;" ::: "memory")

// R13 grid barrier: counting atomic, single hot word, thread-0 poll only.
__device__ __forceinline__ void grid_bar() {
    __threadfence();
    __syncthreads();
    if (threadIdx.x == 0) {
        unsigned int gen = g_bar_gen;
        if (atomicAdd(&g_bar_cnt, 1u) == NB_LSTM - 1) {
            g_bar_cnt = 0;
            __threadfence();
            g_bar_gen = gen + 1;
        } else {
            while (g_bar_gen == gen) { }
            __threadfence();
        }
    }
    __syncthreads();
}

// ----------------------------------------------------------------------------
// Weight prep kernels
// ----------------------------------------------------------------------------
__global__ void wprep(const float* __restrict__ w, __nv_bfloat16* __restrict__ hi,
                      __nv_bfloat16* __restrict__ lo, int total4) {
    int idx = blockIdx.x * blockDim.x + threadIdx.x;
    if (idx >= total4) return;
    float4 a = *(const float4*)(w + (size_t)idx * 4);
    uint32_t h0, h1, l0, l1;
    split2(a.x, a.y, h0, l0);
    split2(a.z, a.w, h1, l1);
    *(uint2*)(hi + (size_t)idx * 4) = make_uint2(h0, h1);
    *(uint2*)(lo + (size_t)idx * 4) = make_uint2(l0, l1);
}

__global__ void wprep_ld(const float* __restrict__ w, __nv_bfloat16* __restrict__ hi,
                         __nv_bfloat16* __restrict__ lo, int rows, int ldw) {
    int idx = blockIdx.x * blockDim.x + threadIdx.x;
    if (idx >= rows * 128) return;
    int row = idx >> 7;
    int k4 = (idx & 127) * 4;
    float4 a = *(const float4*)(w + (size_t)row * ldw + k4);
    uint32_t h0, h1, l0, l1;
    split2(a.x, a.y, h0, l0);
    split2(a.z, a.w, h1, l1);
    *(uint2*)(hi + (size_t)row * 512 + k4) = make_uint2(h0, h1);
    *(uint2*)(lo + (size_t)row * 512 + k4) = make_uint2(l0, l1);
}

__global__ void wcprep_all(const float* __restrict__ w1, const float* __restrict__ w2,
                           const float* __restrict__ w3) {
    int idx = blockIdx.x * blockDim.x + threadIdx.x;
    const float* w;
    __nv_bfloat16 *hi, *lo;
    int taps, local;
    if (idx < 6400) { w = w1; hi = g_cw1h; lo = g_cw1l; taps = 25; local = idx; }
    else if (idx < 8704) { w = w2; hi = g_cw2h; lo = g_cw2l; taps = 9; local = idx - 6400; }
    else if (idx < 11008) { w = w3; hi = g_cw3h; lo = g_cw3l; taps = 9; local = idx - 8704; }
    else return;
    int r = local & 255;
    int t = local >> 8;
    float v = w[r * taps + t];
    __nv_bfloat16 hv = __float2bfloat16(v);
    hi[t * 256 + r] = hv;
    lo[t * 256 + r] = __float2bfloat16(v - __bfloat162float(hv));
}

__global__ void wlstm_prep(const float* __restrict__ whh) {
    int idx = blockIdx.x * blockDim.x + threadIdx.x;
    if (idx >= 2048 * 128) return;
    int row = idx >> 7;
    int k4 = (idx & 127) * 4;
    int g = row >> 9, j = row & 511;
    int blk = j >> 2, jj = j & 3;
    int n = 2 * jj + (g & 1) + 8 * (g >> 1);
    size_t dst = ((size_t)(blk * 16 + n)) * 512 + k4;
    float4 v = *(const float4*)(whh + (size_t)row * 512 + k4);
    uint32_t h0, h1, l0, l1;
    split2(v.x, v.y, h0, l0);
    split2(v.z, v.w, h1, l1);
    *(uint2*)(g_wlh + dst) = make_uint2(h0, h1);
    *(uint2*)(g_wll + dst) = make_uint2(l0, l1);
}

__global__ void pack_hc0(const float* __restrict__ h0, const float* __restrict__ c0,
                         const int* __restrict__ done) {
    int i = blockIdx.x * blockDim.x + threadIdx.x;
    if (i >= B_ENV * HID) return;
    int b = i >> 9;
    float m = done[b] ? 0.f : 1.f;
    float v = h0[i] * m;
    __nv_bfloat16 hv = __float2bfloat16(v);
    g_hhA[i] = hv;
    g_hlA[i] = __float2bfloat16(v - __bfloat162float(hv));
    g_cst[i] = c0[i];
}

// ----------------------------------------------------------------------------
// tgemm2 (proven): pre-split operands, cp.async depth-3 pipeline
// ----------------------------------------------------------------------------
#define SMSTR 80
#define TG_BUF 40960
#define TG_SMEM (4 * TG_BUF)

template <int ACT, int OUTSPLIT, int ZMODE>
__global__ __launch_bounds__(256) void tgemm2(
    const __nv_bfloat16* __restrict__ Ahi, const __nv_bfloat16* __restrict__ Alo,
    const __nv_bfloat16* __restrict__ Whi, const __nv_bfloat16* __restrict__ Wlo,
    const float* __restrict__ bias, const float* __restrict__ bias2,
    float* __restrict__ C, __nv_bfloat16* __restrict__ Chi,
    __nv_bfloat16* __restrict__ Clo,
    const float* __restrict__ Wzf, int ldw, const int* __restrict__ z,
    int M, int N, int K) {
    extern __shared__ uint8_t sm[];
    uint32_t sb = smem_to_u32(sm);
    int tid = threadIdx.x;
    int lane = tid & 31;
    int wid = tid >> 5;
    int wm = wid & 3, wn = wid >> 2;
    int m0 = blockIdx.y * 128, n0 = blockIdx.x * 128;
    int sr0 = tid >> 2, sq = tid & 3;
    int nslab = K / 32;

    float acc[2][8][4];
#pragma unroll
    for (int i = 0; i < 2; i++)
#pragma unroll
        for (int j = 0; j < 8; j++)
#pragma unroll
            for (int q = 0; q < 4; q++) acc[i][j][q] = 0.f;

    auto cpa = [&](int s) {
        uint32_t buf = sb + (uint32_t)((s & 3) * TG_BUF);
        size_t ko = (size_t)s * 32 + sq * 8;
#pragma unroll
        for (int q = 0; q < 2; q++) {
            int r = sr0 + 64 * q;
            uint32_t d = (uint32_t)(r * SMSTR + sq * 16);
            CP_ASYNC16(buf + d,         Ahi + (size_t)(m0 + r) * K + ko);
            CP_ASYNC16(buf + 10240 + d, Alo + (size_t)(m0 + r) * K + ko);
            CP_ASYNC16(buf + 20480 + d, Whi + (size_t)(n0 + r) * K + ko);
            CP_ASYNC16(buf + 30720 + d, Wlo + (size_t)(n0 + r) * K + ko);
        }
        CP_COMMIT();
    };

    cpa(0); cpa(1); cpa(2);

    int g = lane >> 3;
    int arow_off = (lane & 7) + (g & 1) * 8;
    int akb_off = (g >> 1) * 16;
    int brow_off = (lane & 7) + (g >> 1) * 8;
    int bkb_off = (g & 1) * 16;

    for (int s = 0; s < nslab; s++) {
        CP_WAIT2();
        __syncthreads();
        if (s + 3 < nslab) cpa(s + 3);
        else CP_COMMIT();
        uint32_t buf = sb + (uint32_t)((s & 3) * TG_BUF);
#pragma unroll
        for (int kk2 = 0; kk2 < 2; kk2++) {
            int kb = kk2 * 32;
            uint32_t ah[2][4], al[2][4], bh[4][4], bl[4][4];
#pragma unroll
            for (int mi = 0; mi < 2; mi++) {
                uint32_t r = (uint32_t)((wm * 32 + mi * 16 + arow_off) * SMSTR +
                                        kb + akb_off);
                ldsm4(buf + r, ah[mi]);
                ldsm4(buf + 10240 + r, al[mi]);
            }
#pragma unroll
            for (int pi = 0; pi < 4; pi++) {
                uint32_t r = (uint32_t)((wn * 64 + pi * 16 + brow_off) * SMSTR +
                                        kb + bkb_off);
                ldsm4(buf + 20480 + r, bh[pi]);
                ldsm4(buf + 30720 + r, bl[pi]);
            }
#pragma unroll
            for (int mi = 0; mi < 2; mi++)
#pragma unroll
                for (int pi = 0; pi < 4; pi++)
#pragma unroll
                    for (int half = 0; half < 2; half++) {
                        float* d = acc[mi][pi * 2 + half];
                        mma16816(d, ah[mi], &bh[pi][half * 2]);
                        mma16816(d, ah[mi], &bl[pi][half * 2]);
                        mma16816(d, al[mi], &bh[pi][half * 2]);
                    }
        }
    }
    __syncthreads();

    float* ct = (float*)sm;
#pragma unroll
    for (int mi = 0; mi < 2; mi++) {
        int r0 = wm * 32 + mi * 16 + (lane >> 2);
        int z0 = 0, z1 = 0;
        if (ZMODE) {
            z0 = z[m0 + r0];
            z1 = z[m0 + r0 + 8];
        }
#pragma unroll
        for (int ni = 0; ni < 8; ni++) {
            int c = wn * 64 + ni * 8 + (lane & 3) * 2;
            float b0 = bias[n0 + c], b1 = bias[n0 + c + 1];
            if (bias2) { b0 += bias2[n0 + c]; b1 += bias2[n0 + c + 1]; }
            float v0 = acc[mi][ni][0] + b0;
            float v1 = acc[mi][ni][1] + b1;
            float v2 = acc[mi][ni][2] + b0;
            float v3 = acc[mi][ni][3] + b1;
            if (ZMODE) {
                v0 += Wzf[(size_t)(n0 + c) * ldw + 512 + z0];
                v1 += Wzf[(size_t)(n0 + c + 1) * ldw + 512 + z0];
                v2 += Wzf[(size_t)(n0 + c) * ldw + 512 + z1];
                v3 += Wzf[(size_t)(n0 + c + 1) * ldw + 512 + z1];
            }
            if (ACT) {
                v0 = v0 > 0.f ? v0 : 0.01f * v0;
                v1 = v1 > 0.f ? v1 : 0.01f * v1;
                v2 = v2 > 0.f ? v2 : 0.01f * v2;
                v3 = v3 > 0.f ? v3 : 0.01f * v3;
            }
            ct[r0 * 132 + c] = v0;
            ct[r0 * 132 + c + 1] = v1;
            ct[(r0 + 8) * 132 + c] = v2;
            ct[(r0 + 8) * 132 + c + 1] = v3;
        }
    }
    __syncthreads();
    {
        int r8 = tid >> 5;
        int c4 = (tid & 31) * 4;
#pragma unroll
        for (int p = 0; p < 16; p++) {
            int r = p * 8 + r8;
            float4 v = *(const float4*)(ct + r * 132 + c4);
            size_t o = (size_t)(m0 + r) * N + n0 + c4;
            if (OUTSPLIT) {
                uint32_t h0, h1, l0, l1;
                split2(v.x, v.y, h0, l0);
                split2(v.z, v.w, h1, l1);
                *(uint2*)(Chi + o) = make_uint2(h0, h1);
                *(uint2*)(Clo + o) = make_uint2(l0, l1);
            } else {
                *(float4*)(C + o) = v;
            }
        }
    }
}

// ----------------------------------------------------------------------------
// HMMA conv (proven); final layer writes SPLIT bf16 activations
// ----------------------------------------------------------------------------
#define PSTR 48
#define IMG_BYTES (400 * PSTR)
#define CW_OFF   (2 * IMG_BYTES)
#define CW_HALF  12800

template <int KS, int P, int LAST>
__device__ __forceinline__ void conv_hmma_layer(
    uint8_t* csm, uint32_t sbase, const __nv_bfloat16* wsrc_h,
    const __nv_bfloat16* wsrc_l, const float* __restrict__ bias,
    __nv_bfloat16* goh, __nv_bfloat16* gol, int tid, int lane, int wid) {
    const int taps = KS * KS;
    {
        const uint4* sh = (const uint4*)wsrc_h;
        const uint4* sl = (const uint4*)wsrc_l;
        uint4* dh = (uint4*)(csm + CW_OFF);
        uint4* dl = (uint4*)(csm + CW_OFF + CW_HALF);
        for (int i = tid; i < taps * 32; i += 256) {
            dh[i] = sh[i];
            dl[i] = sl[i];
        }
    }
    __syncthreads();

    float acc[2][2][4];
#pragma unroll
    for (int a = 0; a < 2; a++)
#pragma unroll
        for (int b = 0; b < 2; b++)
#pragma unroll
            for (int q = 0; q < 4; q++) acc[a][b][q] = 0.f;

    int g = lane >> 3;
    int h0 = wid * 2;
    uint32_t aoff[2];
#pragma unroll
    for (int mi = 0; mi < 2; mi++)
        aoff[mi] = (uint32_t)(((h0 + mi + 2) * 20 + 2 + (lane & 7) + (g & 1) * 8) * PSTR +
                              (g >> 1) * 16);
    uint32_t boff = (uint32_t)(((lane & 7) + (g >> 1) * 8) * 32 + (g & 1) * 16);
    uint32_t wb_h = sbase + CW_OFF;
    uint32_t wb_l = sbase + CW_OFF + CW_HALF;

#pragma unroll
    for (int kh = 0; kh < KS; kh++) {
#pragma unroll
        for (int kw = 0; kw < KS; kw++) {
            int t = kh * KS + kw;
            int shift = ((kh - P) * 20 + (kw - P)) * PSTR;
            uint32_t bh4[4], bl4[4];
            ldsm4(wb_h + t * 512 + boff, bh4);
            ldsm4(wb_l + t * 512 + boff, bl4);
#pragma unroll
            for (int mi = 0; mi < 2; mi++) {
                uint32_t ah[4], al[4];
                ldsm4(sbase + aoff[mi] + shift, ah);
                ldsm4(sbase + IMG_BYTES + aoff[mi] + shift, al);
#pragma unroll
                for (int nh = 0; nh < 2; nh++) {
                    mma16816(acc[mi][nh], ah, &bh4[nh * 2]);
                    mma16816(acc[mi][nh], ah, &bl4[nh * 2]);
                    mma16816(acc[mi][nh], al, &bh4[nh * 2]);
                }
            }
        }
    }
    __syncthreads();

#pragma unroll
    for (int mi = 0; mi < 2; mi++) {
        int h = h0 + mi;
#pragma unroll
        for (int nh = 0; nh < 2; nh++) {
            int co = nh * 8 + (lane & 3) * 2;
            float b0 = bias[co], b1 = bias[co + 1];
#pragma unroll
            for (int rr = 0; rr < 2; rr++) {
                int w = (lane >> 2) + rr * 8;
                float v0 = acc[mi][nh][rr * 2 + 0] + b0;
                float v1 = acc[mi][nh][rr * 2 + 1] + b1;
                v0 = v0 > 0.f ? v0 : 0.01f * v0;
                v1 = v1 > 0.f ? v1 : 0.01f * v1;
                if (LAST) {
                    int k0 = co * 256 + h * 16 + w;
                    __nv_bfloat16 hv0 = __float2bfloat16(v0);
                    goh[k0] = hv0;
                    gol[k0] = __float2bfloat16(v0 - __bfloat162float(hv0));
                    __nv_bfloat16 hv1 = __float2bfloat16(v1);
                    goh[k0 + 256] = hv1;
                    gol[k0 + 256] = __float2bfloat16(v1 - __bfloat162float(hv1));
                } else {
                    uint32_t hp, lp;
                    split2(v0, v1, hp, lp);
                    int pb = ((h + 2) * 20 + (w + 2)) * PSTR + co * 2;
                    *(uint32_t*)(csm + pb) = hp;
                    *(uint32_t*)(csm + IMG_BYTES + pb) = lp;
                }
            }
        }
    }
    __syncthreads();
}

__global__ __launch_bounds__(256) void conv3_mma(
    const float* __restrict__ x,
    const float* __restrict__ b1, const float* __restrict__ b2,
    const float* __restrict__ b3) {
    extern __shared__ uint8_t csm[];
    uint32_t sbase = smem_to_u32(csm);
    int tid = threadIdx.x;
    int lane = tid & 31;
    int wid = tid >> 5;
    int img = blockIdx.x;
    const float* xi = x + (size_t)img * 4096;

    for (int i = tid; i < 2 * IMG_BYTES / 4; i += 256)
        ((uint32_t*)csm)[i] = 0;
    __syncthreads();
    for (int i = tid; i < 4096; i += 256) {
        int ci = i >> 8, p = i & 255;
        int h = p >> 4, w = p & 15;
        float v = xi[i];
        __nv_bfloat16 hv = __float2bfloat16(v);
        float lv = v - __bfloat162float(hv);
        int pb = ((h + 2) * 20 + (w + 2)) * PSTR + ci * 2;
        *(__nv_bfloat16*)(csm + pb) = hv;
        *(__nv_bfloat16*)(csm + IMG_BYTES + pb) = __float2bfloat16(lv);
    }
    __syncthreads();

    __nv_bfloat16* goh = g_a1h + (size_t)img * 4096;
    __nv_bfloat16* gol = g_a1l + (size_t)img * 4096;
    conv_hmma_layer<5, 2, 0>(csm, sbase, g_cw1h, g_cw1l, b1, goh, gol, tid, lane, wid);
    conv_hmma_layer<3, 1, 0>(csm, sbase, g_cw2h, g_cw2l, b2, goh, gol, tid, lane, wid);
    conv_hmma_layer<3, 1, 1>(csm, sbase, g_cw3h, g_cw3l, b3, goh, gol, tid, lane, wid);
}

// ----------------------------------------------------------------------------
// Persistent LSTM (R13 proven): 64-k slabs, cp.async depth-3, atomic barrier.
// ----------------------------------------------------------------------------
__device__ __forceinline__ float sigm(float x) { return 1.f / (1.f + expf(-x)); }

#define LW_STR   1040
#define LA_STR   144
#define LS_W_SZ  (2 * 16 * LW_STR)
#define LS_A_OFF LS_W_SZ
#define LS_A_BUF (2 * 128 * LA_STR)
#define LS_M_OFF (LS_A_OFF + 4 * LS_A_BUF)
#define LS_SMEM  (LS_M_OFF + 1024)

__global__ __launch_bounds__(256) void lstm_persist(
    const float* __restrict__ xg, const int* __restrict__ done,
    __nv_bfloat16* __restrict__ hAh, __nv_bfloat16* __restrict__ hAl,
    __nv_bfloat16* __restrict__ hBh, __nv_bfloat16* __restrict__ hBl,
    float* __restrict__ c_st) {
    extern __shared__ uint8_t psm[];
    float* s_m  = (float*)(psm + LS_M_OFF);
    float* s_mn = (float*)(psm + LS_M_OFF + 512);
    uint32_t sbW = smem_to_u32(psm);
    int tid = threadIdx.x, lane = tid & 31, wid = tid >> 5;
    int blk = blockIdx.x;
    int jb4 = blk * 4;

    {
        const uint4* Wh = (const uint4*)(g_wlh + (size_t)blk * 16 * 512);
        const uint4* Wl = (const uint4*)(g_wll + (size_t)blk * 16 * 512);
#pragma unroll
        for (int i = 0; i < 4; i++) {
            int i4 = tid + 256 * i;
            int r = i4 >> 6, q = i4 & 63;
            *(uint4*)(psm + r * LW_STR + q * 16) = Wh[i4];
            *(uint4*)(psm + 16 * LW_STR + r * LW_STR + q * 16) = Wl[i4];
        }
    }

    int r1 = wid * 16 + (lane >> 2);
    int L = lane & 3;
    int gq = lane >> 3;
    uint32_t arow = (uint32_t)((wid * 16 + (lane & 7) + (gq & 1) * 8) * LA_STR +
                               (gq >> 1) * 16);
    uint32_t brow = (uint32_t)(((lane & 7) + (gq >> 1) * 8) * LW_STR + (gq & 1) * 16);

    float creg[2];
#pragma unroll
    for (int rr = 0; rr < 2; rr++)
        creg[rr] = c_st[(size_t)(r1 + rr * 8) * 512 + jb4 + L];
    __syncthreads();

    for (int t = 0; t < T_STEPS; t++) {
        const __nv_bfloat16* hih = (t & 1) ? hBh : hAh;
        const __nv_bfloat16* hil = (t & 1) ? hBl : hAl;
        __nv_bfloat16* hoh = (t & 1) ? hAh : hBh;
        __nv_bfloat16* hol = (t & 1) ? hAl : hBl;

        auto cpa_slab = [&](int s) {
            uint32_t base = sbW + LS_A_OFF + (uint32_t)((s & 3) * LS_A_BUF);
#pragma unroll
            for (int i = 0; i < 4; i++) {
                int idx = tid + 256 * i;
                int r = idx >> 3, ch = idx & 7;
                CP_ASYNC16(base + r * LA_STR + ch * 16,
                           hih + (size_t)r * 512 + s * 64 + ch * 8);
                CP_ASYNC16(base + 128 * LA_STR + r * LA_STR + ch * 16,
                           hil + (size_t)r * 512 + s * 64 + ch * 8);
            }
            CP_COMMIT();
        };

        cpa_slab(0);
        cpa_slab(1);
        cpa_slab(2);

        if (tid < 128) {
            s_m[tid] = done[t * 128 + tid] ? 0.f : 1.f;
            s_mn[tid] = (t + 1 < T_STEPS)
                            ? (done[(t + 1) * 128 + tid] ? 0.f : 1.f) : 1.f;
        }

        float acc[2][4];
#pragma unroll
        for (int pi = 0; pi < 2; pi++)
#pragma unroll
            for (int rr = 0; rr < 2; rr++)
#pragma unroll
                for (int cc = 0; cc < 2; cc++)
                    acc[pi][rr * 2 + cc] = xg[(size_t)(t * 128 + r1 + rr * 8) * 2048 +
                                              (cc + 2 * pi) * 512 + jb4 + L];

        for (int s = 0; s < 8; s++) {
            CP_WAIT2();
            __syncthreads();
            if (s < 5) cpa_slab(s + 3);
            else CP_COMMIT();
            uint32_t sbA = sbW + LS_A_OFF + (uint32_t)((s & 3) * LS_A_BUF);
#pragma unroll
            for (int kk2 = 0; kk2 < 4; kk2++) {
                int kb = kk2 * 32;
                uint32_t ah[4], al[4], bh4[4], bl4[4];
                ldsm4(sbA + arow + kb, ah);
                ldsm4(sbA + 128 * LA_STR + arow + kb, al);
                uint32_t bo = brow + s * 128 + kb;
                ldsm4(sbW + bo, bh4);
                ldsm4(sbW + 16 * LW_STR + bo, bl4);
#pragma unroll
                for (int pi = 0; pi < 2; pi++) {
                    float* d = acc[pi];
                    mma16816(d, ah, &bh4[pi * 2]);
                    mma16816(d, ah, &bl4[pi * 2]);
                    mma16816(d, al, &bh4[pi * 2]);
                }
            }
        }

#pragma unroll
        for (int rr = 0; rr < 2; rr++) {
            int r = r1 + rr * 8;
            float m = s_m[r];
            float mn = s_mn[r];
            int j = jb4 + L;
            float gi = acc[0][rr * 2 + 0];
            float gf = acc[0][rr * 2 + 1];
            float gg = acc[1][rr * 2 + 0];
            float go = acc[1][rr * 2 + 1];
            float cn = sigm(gf) * (creg[rr] * m) + sigm(gi) * tanhf(gg);
            float hn = sigm(go) * tanhf(cn);
            creg[rr] = cn;
            size_t fo = (size_t)(t * 128 + r) * 512 + j;
            __nv_bfloat16 fh = __float2bfloat16(hn);
            g_feath[fo] = fh;
            g_featl[fo] = __float2bfloat16(hn - __bfloat162float(fh));
            float hw = hn * mn;
            __nv_bfloat16 hh = __float2bfloat16(hw);
            hoh[(size_t)r * 512 + j] = hh;
            hol[(size_t)r * 512 + j] = __float2bfloat16(hw - __bfloat162float(hh));
        }
        grid_bar();
    }
}

// ----------------------------------------------------------------------------
// Head: warp per row; actor/critic GEMV + log_softmax/entropy/prob pack.
// ----------------------------------------------------------------------------
__global__ __launch_bounds__(256) void head_kernel(
    const float* __restrict__ lf, const float* __restrict__ aw,
    const float* __restrict__ ab, const float* __restrict__ cw,
    const float* __restrict__ cb, const int* __restrict__ action,
    float* __restrict__ out) {
    int warp = (blockIdx.x * blockDim.x + threadIdx.x) >> 5;
    int lane = threadIdx.x & 31;
    if (warp >= TBTOT) return;
    float4 f = *(const float4*)(lf + (size_t)warp * FE + lane * 4);
    float r[8];
#pragma unroll
    for (int a = 0; a < 7; a++) {
        float4 w = *(const float4*)(aw + a * FE + lane * 4);
        r[a] = f.x * w.x + f.y * w.y + f.z * w.z + f.w * w.w;
    }
    {
        float4 w = *(const float4*)(cw + lane * 4);
        r[7] = f.x * w.x + f.y * w.y + f.z * w.z + f.w * w.w;
    }
#pragma unroll
    for (int a = 0; a < 8; a++)
#pragma unroll
        for (int s = 16; s > 0; s >>= 1)
            r[a] += __shfl_xor_sync(0xffffffffu, r[a], s);

    if (lane == 0) {
        float lg[7];
        float mx = -1e30f;
#pragma unroll
        for (int a = 0; a < 7; a++) {
            lg[a] = r[a] + ab[a];
            mx = fmaxf(mx, lg[a]);
        }
        float se = 0.f;
        float e[7];
#pragma unroll
        for (int a = 0; a < 7; a++) {
            e[a] = expf(lg[a] - mx);
            se += e[a];
        }
        float lse = mx + logf(se);
        float inv = 1.f / se;
        float ent = 0.f;
        float* o = out + (size_t)warp * 10;
#pragma unroll
        for (int a = 0; a < 7; a++) {
            float p = e[a] * inv;
            float lp = lg[a] - lse;
            ent -= p * lp;
            o[3 + a] = p;
        }
        int act = action[warp];
        o[0] = lg[act] - lse;
        o[1] = ent;
        o[2] = r[7] + cb[0];
    }
}

// ----------------------------------------------------------------------------
// Launch (fork-join second stream overlaps preps with conv)
// ----------------------------------------------------------------------------
extern "C" void kernel_launch(void* const* d_in, const int* in_sizes, int n_in,
                              void* d_out, int out_size) {
    const float* x    = (const float*)d_in[0];
    const int* done   = (const int*)d_in[1];
    const int* z      = (const int*)d_in[2];
    const int* action = (const int*)d_in[3];
    const float* h0   = (const float*)d_in[4];
    const float* c0   = (const float*)d_in[5];
    const float* c1w = (const float*)d_in[6];  const float* c1b = (const float*)d_in[7];
    const float* c2w = (const float*)d_in[8];  const float* c2b = (const float*)d_in[9];
    const float* c3w = (const float*)d_in[10]; const float* c3b = (const float*)d_in[11];
    const float* fc1w = (const float*)d_in[12]; const float* fc1b = (const float*)d_in[13];
    const float* fc2w = (const float*)d_in[14]; const float* fc2b = (const float*)d_in[15];
    const float* wih = (const float*)d_in[16]; const float* whh = (const float*)d_in[17];
    const float* bih = (const float*)d_in[18]; const float* bhh = (const float*)d_in[19];
    const float* lfw = (const float*)d_in[20]; const float* lfb = (const float*)d_in[21];
    const float* aw = (const float*)d_in[22];  const float* ab = (const float*)d_in[23];
    const float* cw = (const float*)d_in[24];  const float* cb = (const float*)d_in[25];
    float* out = (float*)d_out;

    float *pxg, *plf, *pcst;
    __nv_bfloat16 *pa1h, *pa1l, *ph1h, *ph1l, *ph2h, *ph2l, *pfh, *pfl;
    __nv_bfloat16 *pw1h, *pw1l, *pw2h, *pw2l, *pwih_h, *pwih_l, *pwlfh, *pwlfl;
    __nv_bfloat16 *phhA, *phlA, *phhB, *phlB;
    cudaGetSymbolAddress((void**)&pa1h, g_a1h);
    cudaGetSymbolAddress((void**)&pa1l, g_a1l);
    cudaGetSymbolAddress((void**)&ph1h, g_h1h);
    cudaGetSymbolAddress((void**)&ph1l, g_h1l);
    cudaGetSymbolAddress((void**)&ph2h, g_h2h);
    cudaGetSymbolAddress((void**)&ph2l, g_h2l);
    cudaGetSymbolAddress((void**)&pxg, g_xg);
    cudaGetSymbolAddress((void**)&pfh, g_feath);
    cudaGetSymbolAddress((void**)&pfl, g_featl);
    cudaGetSymbolAddress((void**)&plf, g_lf);
    cudaGetSymbolAddress((void**)&pcst, g_cst);
    cudaGetSymbolAddress((void**)&phhA, g_hhA);
    cudaGetSymbolAddress((void**)&phlA, g_hlA);
    cudaGetSymbolAddress((void**)&phhB, g_hhB);
    cudaGetSymbolAddress((void**)&phlB, g_hlB);
    cudaGetSymbolAddress((void**)&pw1h, g_wfc1_hi);
    cudaGetSymbolAddress((void**)&pw1l, g_wfc1_lo);
    cudaGetSymbolAddress((void**)&pw2h, g_wfc2_hi);
    cudaGetSymbolAddress((void**)&pw2l, g_wfc2_lo);
    cudaGetSymbolAddress((void**)&pwih_h, g_wih_hi);
    cudaGetSymbolAddress((void**)&pwih_l, g_wih_lo);
    cudaGetSymbolAddress((void**)&pwlfh, g_wlf_hi);
    cudaGetSymbolAddress((void**)&pwlfl, g_wlf_lo);

    cudaFuncSetAttribute(tgemm2<1, 1, 0>, cudaFuncAttributeMaxDynamicSharedMemorySize, TG_SMEM);
    cudaFuncSetAttribute(tgemm2<0, 0, 0>, cudaFuncAttributeMaxDynamicSharedMemorySize, TG_SMEM);
    cudaFuncSetAttribute(tgemm2<1, 0, 1>, cudaFuncAttributeMaxDynamicSharedMemorySize, TG_SMEM);
    const int SMEM_CONV = 2 * IMG_BYTES + 2 * CW_HALF;
    cudaFuncSetAttribute(conv3_mma, cudaFuncAttributeMaxDynamicSharedMemorySize, SMEM_CONV);
    cudaFuncSetAttribute(lstm_persist, cudaFuncAttributeMaxDynamicSharedMemorySize, LS_SMEM);

    static cudaStream_t s2 = nullptr;
    static cudaEvent_t evF = nullptr, evJ = nullptr;
    if (s2 == nullptr) {
        cudaStreamCreateWithFlags(&s2, cudaStreamNonBlocking);
        cudaEventCreateWithFlags(&evF, cudaEventDisableTiming);
        cudaEventCreateWithFlags(&evJ, cudaEventDisableTiming);
    }

    // conv weight prep must precede conv (stream 0)
    wcprep_all<<<(11008 + 255) / 256, 256>>>(c1w, c2w, c3w);

    // fork: all other preps run on s2, concurrent with conv
    cudaEventRecord(evF, 0);
    cudaStreamWaitEvent(s2, evF, 0);
    wprep<<<(512 * 1024 + 255) / 256, 256, 0, s2>>>(fc1w, pw1h, pw1l, 512 * 1024);
    wprep<<<(512 * 128 + 255) / 256, 256, 0, s2>>>(fc2w, pw2h, pw2l, 512 * 128);
    wprep<<<(2048 * 128 + 255) / 256, 256, 0, s2>>>(wih, pwih_h, pwih_l, 2048 * 128);
    wprep_ld<<<(128 * 128 + 255) / 256, 256, 0, s2>>>(lfw, pwlfh, pwlfl, 128, 520);
    wlstm_prep<<<(2048 * 128 + 255) / 256, 256, 0, s2>>>(whh);
    pack_hc0<<<(B_ENV * HID + 255) / 256, 256, 0, s2>>>(h0, c0, done);
    cudaEventRecord(evJ, s2);

    // conv on stream 0 (overlaps s2)
    conv3_mma<<<TBTOT, 256, SMEM_CONV>>>(x, c1b, c2b, c3b);

    // join before fc1
    cudaStreamWaitEvent(0, evJ, 0);

    tgemm2<1, 1, 0><<<dim3(4, 128), 256, TG_SMEM>>>(
        pa1h, pa1l, pw1h, pw1l, fc1b, nullptr,
        nullptr, ph1h, ph1l, nullptr, 0, nullptr, TBTOT, 512, 4096);
    tgemm2<1, 1, 0><<<dim3(4, 128), 256, TG_SMEM>>>(
        ph1h, ph1l, pw2h, pw2l, fc2b, nullptr,
        nullptr, ph2h, ph2l, nullptr, 0, nullptr, TBTOT, 512, 512);
    tgemm2<0, 0, 0><<<dim3(16, 128), 256, TG_SMEM>>>(
        ph2h, ph2l, pwih_h, pwih_l, bih, bhh,
        pxg, nullptr, nullptr, nullptr, 0, nullptr, TBTOT, 2048, 512);

    lstm_persist<<<NB_LSTM, 256, LS_SMEM>>>(pxg, done, phhA, phlA, phhB, phlB,
                                            pcst);

    tgemm2<1, 0, 1><<<dim3(1, 128), 256, TG_SMEM>>>(
        pfh, pfl, pwlfh, pwlfl, lfb, nullptr,
        plf, nullptr, nullptr, lfw, 520, z, TBTOT, FE, 512);

    head_kernel<<<TBTOT / 8, 256>>>(plf, aw, ab, cw, cb, action, out);
}

// round 16
// speedup vs baseline: 1.6674x; 1.3202x over previous
#include <cuda_runtime.h>
#include <cuda_fp16.h>
#include <math.h>
#include <stdint.h>

#define T_STEPS 128
#define B_ENV   128
#define HID     512
#define TBTOT   (T_STEPS * B_ENV)
#define ZD      8
#define AD      7
#define FE      128
#define NB_LSTM 128

// ----------------------------------------------------------------------------
// Scratch (device globals; no allocation allowed)
// ----------------------------------------------------------------------------
__device__ __half g_a1[TBTOT * 4096];
__device__ __half g_h1[TBTOT * HID];
__device__ __half g_h2[TBTOT * HID];
__device__ float g_xg[TBTOT * 2048];
__device__ __half g_feat[TBTOT * HID];
__device__ float g_lf[TBTOT * FE];
__device__ float g_cst[B_ENV * HID];
__device__ __half g_hA[B_ENV * HID];
__device__ __half g_hB[B_ENV * HID];
// weights: fp16 2-term split (hi + residual lo)
__device__ __half g_wlh[128 * 16 * 512];
__device__ __half g_wll[128 * 16 * 512];
__device__ __half g_wfc1_hi[512 * 4096];
__device__ __half g_wfc1_lo[512 * 4096];
__device__ __half g_wfc2_hi[512 * 512];
__device__ __half g_wfc2_lo[512 * 512];
__device__ __half g_wih_hi[2048 * 512];
__device__ __half g_wih_lo[2048 * 512];
__device__ __half g_wlf_hi[128 * 512];
__device__ __half g_wlf_lo[128 * 512];
__device__ __half g_cw1h[25 * 256];
__device__ __half g_cw1l[25 * 256];
__device__ __half g_cw2h[9 * 256];
__device__ __half g_cw2l[9 * 256];
__device__ __half g_cw3h[9 * 256];
__device__ __half g_cw3l[9 * 256];
// grid barrier (R13 proven)
__device__ unsigned int g_bar_cnt;
__device__ volatile unsigned int g_bar_gen;

// ============================================================================
// Helpers
// ============================================================================
__device__ __forceinline__ uint32_t smem_to_u32(const void* smem_ptr) {
    uint32_t addr;
    asm("{ .reg .u64 tmp; cvta.to.shared.u64 tmp, %1; cvt.u32.u64 %0, tmp; }"
        : "=r"(addr) : "l"(smem_ptr));
    return addr;
}

__device__ __forceinline__ void ldsm4(uint32_t addr, uint32_t* r) {
    asm volatile("ldmatrix.sync.aligned.m8n8.x4.shared.b16 {%0,%1,%2,%3}, [%4];"
        : "=r"(r[0]), "=r"(r[1]), "=r"(r[2]), "=r"(r[3]) : "r"(addr));
}

__device__ __forceinline__ void mma16816(float* d, const uint32_t* a,
                                         const uint32_t* b) {
    asm volatile(
        "mma.sync.aligned.m16n8k16.row.col.f32.f16.f16.f32 "
        "{%0,%1,%2,%3}, {%4,%5,%6,%7}, {%8,%9}, {%0,%1,%2,%3};"
        : "+f"(d[0]), "+f"(d[1]), "+f"(d[2]), "+f"(d[3])
        : "r"(a[0]), "r"(a[1]), "r"(a[2]), "r"(a[3]), "r"(b[0]), "r"(b[1]));
}

__device__ __forceinline__ void hsplit(float v, __half& hi, __half& lo) {
    hi = __float2half(v);
    lo = __float2half(v - __half2float(hi));
}

#define CP_ASYNC16(dst, src) \
    asm volatile("cp.async.ca.shared.global [%0], [%1], 16;" \
        :: "r"(dst), "l"(src) : "memory")
#define CP_COMMIT() asm volatile("cp.async.commit_group;" ::: "memory")
#define CP_WAIT2() asm volatile("cp.async.wait_group 2;" ::: "memory")

__device__ __forceinline__ void grid_bar() {
    __threadfence();
    __syncthreads();
    if (threadIdx.x == 0) {
        unsigned int gen = g_bar_gen;
        if (atomicAdd(&g_bar_cnt, 1u) == NB_LSTM - 1) {
            g_bar_cnt = 0;
            __threadfence();
            g_bar_gen = gen + 1;
        } else {
            while (g_bar_gen == gen) { }
            __threadfence();
        }
    }
    __syncthreads();
}

// ----------------------------------------------------------------------------
// Weight prep kernels (fp16 2-term split)
// ----------------------------------------------------------------------------
__global__ void wprep(const float* __restrict__ w, __half* __restrict__ hi,
                      __half* __restrict__ lo, int total) {
    int idx = blockIdx.x * blockDim.x + threadIdx.x;
    if (idx >= total) return;
    __half h, l;
    hsplit(w[idx], h, l);
    hi[idx] = h;
    lo[idx] = l;
}

__global__ void wprep_ld(const float* __restrict__ w, __half* __restrict__ hi,
                         __half* __restrict__ lo, int rows, int ldw) {
    int idx = blockIdx.x * blockDim.x + threadIdx.x;
    if (idx >= rows * 512) return;
    int row = idx >> 9;
    int k = idx & 511;
    __half h, l;
    hsplit(w[(size_t)row * ldw + k], h, l);
    hi[(size_t)row * 512 + k] = h;
    lo[(size_t)row * 512 + k] = l;
}

__global__ void wcprep_all(const float* __restrict__ w1, const float* __restrict__ w2,
                           const float* __restrict__ w3) {
    int idx = blockIdx.x * blockDim.x + threadIdx.x;
    const float* w;
    __half *hi, *lo;
    int taps, local;
    if (idx < 6400) { w = w1; hi = g_cw1h; lo = g_cw1l; taps = 25; local = idx; }
    else if (idx < 8704) { w = w2; hi = g_cw2h; lo = g_cw2l; taps = 9; local = idx - 6400; }
    else if (idx < 11008) { w = w3; hi = g_cw3h; lo = g_cw3l; taps = 9; local = idx - 8704; }
    else return;
    int r = local & 255;
    int t = local >> 8;
    __half h, l;
    hsplit(w[r * taps + t], h, l);
    hi[t * 256 + r] = h;
    lo[t * 256 + r] = l;
}

__global__ void wlstm_prep(const float* __restrict__ whh) {
    int idx = blockIdx.x * blockDim.x + threadIdx.x;
    if (idx >= 2048 * 512) return;
    int row = idx >> 9;
    int k = idx & 511;
    int g = row >> 9, j = row & 511;
    int blk = j >> 2, jj = j & 3;
    int n = 2 * jj + (g & 1) + 8 * (g >> 1);
    size_t dst = ((size_t)(blk * 16 + n)) * 512 + k;
    __half h, l;
    hsplit(whh[(size_t)row * 512 + k], h, l);
    g_wlh[dst] = h;
    g_wll[dst] = l;
}

__global__ void pack_hc0(const float* __restrict__ h0, const float* __restrict__ c0,
                         const int* __restrict__ done) {
    int i = blockIdx.x * blockDim.x + threadIdx.x;
    if (i >= B_ENV * HID) return;
    int b = i >> 9;
    float m = done[b] ? 0.f : 1.f;
    g_hA[i] = __float2half(h0[i] * m);
    g_cst[i] = c0[i];
}

// ----------------------------------------------------------------------------
// tgemm2 fp16: A single fp16, W hi/lo fp16. cp.async depth-3, 4 buffers.
// ----------------------------------------------------------------------------
#define SMSTR 80
#define TG_BUF 30720    // per-stage: A | Wh | Wl, each 10240
#define TG_SMEM (4 * TG_BUF)

template <int ACT, int OUTHALF, int ZMODE>
__global__ __launch_bounds__(256) void tgemm2(
    const __half* __restrict__ A,
    const __half* __restrict__ Whi, const __half* __restrict__ Wlo,
    const float* __restrict__ bias, const float* __restrict__ bias2,
    float* __restrict__ C, __half* __restrict__ Ch,
    const float* __restrict__ Wzf, int ldw, const int* __restrict__ z,
    int M, int N, int K) {
    extern __shared__ uint8_t sm[];
    uint32_t sb = smem_to_u32(sm);
    int tid = threadIdx.x;
    int lane = tid & 31;
    int wid = tid >> 5;
    int wm = wid & 3, wn = wid >> 2;
    int m0 = blockIdx.y * 128, n0 = blockIdx.x * 128;
    int sr0 = tid >> 2, sq = tid & 3;
    int nslab = K / 32;

    float acc[2][8][4];
#pragma unroll
    for (int i = 0; i < 2; i++)
#pragma unroll
        for (int j = 0; j < 8; j++)
#pragma unroll
            for (int q = 0; q < 4; q++) acc[i][j][q] = 0.f;

    auto cpa = [&](int s) {
        uint32_t buf = sb + (uint32_t)((s & 3) * TG_BUF);
        size_t ko = (size_t)s * 32 + sq * 8;
#pragma unroll
        for (int q = 0; q < 2; q++) {
            int r = sr0 + 64 * q;
            uint32_t d = (uint32_t)(r * SMSTR + sq * 16);
            CP_ASYNC16(buf + d,         A + (size_t)(m0 + r) * K + ko);
            CP_ASYNC16(buf + 10240 + d, Whi + (size_t)(n0 + r) * K + ko);
            CP_ASYNC16(buf + 20480 + d, Wlo + (size_t)(n0 + r) * K + ko);
        }
        CP_COMMIT();
    };

    cpa(0); cpa(1); cpa(2);

    int g = lane >> 3;
    int arow_off = (lane & 7) + (g & 1) * 8;
    int akb_off = (g >> 1) * 16;
    int brow_off = (lane & 7) + (g >> 1) * 8;
    int bkb_off = (g & 1) * 16;

    for (int s = 0; s < nslab; s++) {
        CP_WAIT2();
        __syncthreads();
        if (s + 3 < nslab) cpa(s + 3);
        else CP_COMMIT();
        uint32_t buf = sb + (uint32_t)((s & 3) * TG_BUF);
#pragma unroll
        for (int kk2 = 0; kk2 < 2; kk2++) {
            int kb = kk2 * 32;
            uint32_t ah[2][4], bh[4][4], bl[4][4];
#pragma unroll
            for (int mi = 0; mi < 2; mi++) {
                uint32_t r = (uint32_t)((wm * 32 + mi * 16 + arow_off) * SMSTR +
                                        kb + akb_off);
                ldsm4(buf + r, ah[mi]);
            }
#pragma unroll
            for (int pi = 0; pi < 4; pi++) {
                uint32_t r = (uint32_t)((wn * 64 + pi * 16 + brow_off) * SMSTR +
                                        kb + bkb_off);
                ldsm4(buf + 10240 + r, bh[pi]);
                ldsm4(buf + 20480 + r, bl[pi]);
            }
#pragma unroll
            for (int mi = 0; mi < 2; mi++)
#pragma unroll
                for (int pi = 0; pi < 4; pi++)
#pragma unroll
                    for (int half = 0; half < 2; half++) {
                        float* d = acc[mi][pi * 2 + half];
                        mma16816(d, ah[mi], &bh[pi][half * 2]);
                        mma16816(d, ah[mi], &bl[pi][half * 2]);
                    }
        }
    }
    __syncthreads();

    float* ct = (float*)sm;
#pragma unroll
    for (int mi = 0; mi < 2; mi++) {
        int r0 = wm * 32 + mi * 16 + (lane >> 2);
        int z0 = 0, z1 = 0;
        if (ZMODE) {
            z0 = z[m0 + r0];
            z1 = z[m0 + r0 + 8];
        }
#pragma unroll
        for (int ni = 0; ni < 8; ni++) {
            int c = wn * 64 + ni * 8 + (lane & 3) * 2;
            float b0 = bias[n0 + c], b1 = bias[n0 + c + 1];
            if (bias2) { b0 += bias2[n0 + c]; b1 += bias2[n0 + c + 1]; }
            float v0 = acc[mi][ni][0] + b0;
            float v1 = acc[mi][ni][1] + b1;
            float v2 = acc[mi][ni][2] + b0;
            float v3 = acc[mi][ni][3] + b1;
            if (ZMODE) {
                v0 += Wzf[(size_t)(n0 + c) * ldw + 512 + z0];
                v1 += Wzf[(size_t)(n0 + c + 1) * ldw + 512 + z0];
                v2 += Wzf[(size_t)(n0 + c) * ldw + 512 + z1];
                v3 += Wzf[(size_t)(n0 + c + 1) * ldw + 512 + z1];
            }
            if (ACT) {
                v0 = v0 > 0.f ? v0 : 0.01f * v0;
                v1 = v1 > 0.f ? v1 : 0.01f * v1;
                v2 = v2 > 0.f ? v2 : 0.01f * v2;
                v3 = v3 > 0.f ? v3 : 0.01f * v3;
            }
            ct[r0 * 132 + c] = v0;
            ct[r0 * 132 + c + 1] = v1;
            ct[(r0 + 8) * 132 + c] = v2;
            ct[(r0 + 8) * 132 + c + 1] = v3;
        }
    }
    __syncthreads();
    {
        int r8 = tid >> 5;
        int c4 = (tid & 31) * 4;
#pragma unroll
        for (int p = 0; p < 16; p++) {
            int r = p * 8 + r8;
            float4 v = *(const float4*)(ct + r * 132 + c4);
            size_t o = (size_t)(m0 + r) * N + n0 + c4;
            if (OUTHALF) {
                __half2 p0 = __floats2half2_rn(v.x, v.y);
                __half2 p1 = __floats2half2_rn(v.z, v.w);
                *(__half2*)(Ch + o) = p0;
                *(__half2*)(Ch + o + 2) = p1;
            } else {
                *(float4*)(C + o) = v;
            }
        }
    }
}

// ----------------------------------------------------------------------------
// HMMA conv, fp16: single-precision activations, W hi/lo. 2 MMA per tap-pair.
// ----------------------------------------------------------------------------
#define PSTR 48
#define IMG_BYTES (400 * PSTR)      // single image copy: 19200
#define CW_OFF   IMG_BYTES
#define CW_HALF  12800

template <int KS, int P, int LAST>
__device__ __forceinline__ void conv_hmma_layer(
    uint8_t* csm, uint32_t sbase, const __half* wsrc_h,
    const __half* wsrc_l, const float* __restrict__ bias,
    __half* go, int tid, int lane, int wid) {
    const int taps = KS * KS;
    {
        const uint4* sh = (const uint4*)wsrc_h;
        const uint4* sl = (const uint4*)wsrc_l;
        uint4* dh = (uint4*)(csm + CW_OFF);
        uint4* dl = (uint4*)(csm + CW_OFF + CW_HALF);
        for (int i = tid; i < taps * 32; i += 256) {
            dh[i] = sh[i];
            dl[i] = sl[i];
        }
    }
    __syncthreads();

    float acc[2][2][4];
#pragma unroll
    for (int a = 0; a < 2; a++)
#pragma unroll
        for (int b = 0; b < 2; b++)
#pragma unroll
            for (int q = 0; q < 4; q++) acc[a][b][q] = 0.f;

    int g = lane >> 3;
    int h0 = wid * 2;
    uint32_t aoff[2];
#pragma unroll
    for (int mi = 0; mi < 2; mi++)
        aoff[mi] = (uint32_t)(((h0 + mi + 2) * 20 + 2 + (lane & 7) + (g & 1) * 8) * PSTR +
                              (g >> 1) * 16);
    uint32_t boff = (uint32_t)(((lane & 7) + (g >> 1) * 8) * 32 + (g & 1) * 16);
    uint32_t wb_h = sbase + CW_OFF;
    uint32_t wb_l = sbase + CW_OFF + CW_HALF;

#pragma unroll
    for (int kh = 0; kh < KS; kh++) {
#pragma unroll
        for (int kw = 0; kw < KS; kw++) {
            int t = kh * KS + kw;
            int shift = ((kh - P) * 20 + (kw - P)) * PSTR;
            uint32_t bh4[4], bl4[4];
            ldsm4(wb_h + t * 512 + boff, bh4);
            ldsm4(wb_l + t * 512 + boff, bl4);
#pragma unroll
            for (int mi = 0; mi < 2; mi++) {
                uint32_t ah[4];
                ldsm4(sbase + aoff[mi] + shift, ah);
#pragma unroll
                for (int nh = 0; nh < 2; nh++) {
                    mma16816(acc[mi][nh], ah, &bh4[nh * 2]);
                    mma16816(acc[mi][nh], ah, &bl4[nh * 2]);
                }
            }
        }
    }
    __syncthreads();

#pragma unroll
    for (int mi = 0; mi < 2; mi++) {
        int h = h0 + mi;
#pragma unroll
        for (int nh = 0; nh < 2; nh++) {
            int co = nh * 8 + (lane & 3) * 2;
            float b0 = bias[co], b1 = bias[co + 1];
#pragma unroll
            for (int rr = 0; rr < 2; rr++) {
                int w = (lane >> 2) + rr * 8;
                float v0 = acc[mi][nh][rr * 2 + 0] + b0;
                float v1 = acc[mi][nh][rr * 2 + 1] + b1;
                v0 = v0 > 0.f ? v0 : 0.01f * v0;
                v1 = v1 > 0.f ? v1 : 0.01f * v1;
                if (LAST) {
                    int k0 = co * 256 + h * 16 + w;
                    go[k0] = __float2half(v0);
                    go[k0 + 256] = __float2half(v1);
                } else {
                    int pb = ((h + 2) * 20 + (w + 2)) * PSTR + co * 2;
                    *(__half2*)(csm + pb) = __floats2half2_rn(v0, v1);
                }
            }
        }
    }
    __syncthreads();
}

__global__ __launch_bounds__(256) void conv3_mma(
    const float* __restrict__ x,
    const float* __restrict__ b1, const float* __restrict__ b2,
    const float* __restrict__ b3) {
    extern __shared__ uint8_t csm[];
    uint32_t sbase = smem_to_u32(csm);
    int tid = threadIdx.x;
    int lane = tid & 31;
    int wid = tid >> 5;
    int img = blockIdx.x;
    const float* xi = x + (size_t)img * 4096;

    for (int i = tid; i < IMG_BYTES / 4; i += 256)
        ((uint32_t*)csm)[i] = 0;
    __syncthreads();
    for (int i = tid; i < 4096; i += 256) {
        int ci = i >> 8, p = i & 255;
        int h = p >> 4, w = p & 15;
        int pb = ((h + 2) * 20 + (w + 2)) * PSTR + ci * 2;
        *(__half*)(csm + pb) = __float2half(xi[i]);
    }
    __syncthreads();

    __half* go = g_a1 + (size_t)img * 4096;
    conv_hmma_layer<5, 2, 0>(csm, sbase, g_cw1h, g_cw1l, b1, go, tid, lane, wid);
    conv_hmma_layer<3, 1, 0>(csm, sbase, g_cw2h, g_cw2l, b2, go, tid, lane, wid);
    conv_hmma_layer<3, 1, 1>(csm, sbase, g_cw3h, g_cw3l, b3, go, tid, lane, wid);
}

// ----------------------------------------------------------------------------
// Persistent LSTM fp16: single-fp16 h, W hi/lo resident; 64-k slabs, depth-3.
// ----------------------------------------------------------------------------
__device__ __forceinline__ float sigm(float x) { return 1.f / (1.f + expf(-x)); }

#define LW_STR   1040
#define LA_STR   144
#define LS_W_SZ  (2 * 16 * LW_STR)                 // 33280
#define LS_A_OFF LS_W_SZ
#define LS_A_BUF (128 * LA_STR)                    // 18432 (single copy)
#define LS_M_OFF (LS_A_OFF + 4 * LS_A_BUF)         // 107008
#define LS_SMEM  (LS_M_OFF + 1024)                 // 108032

__global__ __launch_bounds__(256) void lstm_persist(
    const float* __restrict__ xg, const int* __restrict__ done,
    __half* __restrict__ hA, __half* __restrict__ hB,
    float* __restrict__ c_st) {
    extern __shared__ uint8_t psm[];
    float* s_m  = (float*)(psm + LS_M_OFF);
    float* s_mn = (float*)(psm + LS_M_OFF + 512);
    uint32_t sbW = smem_to_u32(psm);
    int tid = threadIdx.x, lane = tid & 31, wid = tid >> 5;
    int blk = blockIdx.x;
    int jb4 = blk * 4;

    {
        const uint4* Wh = (const uint4*)(g_wlh + (size_t)blk * 16 * 512);
        const uint4* Wl = (const uint4*)(g_wll + (size_t)blk * 16 * 512);
#pragma unroll
        for (int i = 0; i < 4; i++) {
            int i4 = tid + 256 * i;
            int r = i4 >> 6, q = i4 & 63;
            *(uint4*)(psm + r * LW_STR + q * 16) = Wh[i4];
            *(uint4*)(psm + 16 * LW_STR + r * LW_STR + q * 16) = Wl[i4];
        }
    }

    int r1 = wid * 16 + (lane >> 2);
    int L = lane & 3;
    int gq = lane >> 3;
    uint32_t arow = (uint32_t)((wid * 16 + (lane & 7) + (gq & 1) * 8) * LA_STR +
                               (gq >> 1) * 16);
    uint32_t brow = (uint32_t)(((lane & 7) + (gq >> 1) * 8) * LW_STR + (gq & 1) * 16);

    float creg[2];
#pragma unroll
    for (int rr = 0; rr < 2; rr++)
        creg[rr] = c_st[(size_t)(r1 + rr * 8) * 512 + jb4 + L];
    __syncthreads();

    for (int t = 0; t < T_STEPS; t++) {
        const __half* hin = (t & 1) ? hB : hA;
        __half* hout = (t & 1) ? hA : hB;

        auto cpa_slab = [&](int s) {
            uint32_t base = sbW + LS_A_OFF + (uint32_t)((s & 3) * LS_A_BUF);
#pragma unroll
            for (int i = 0; i < 4; i++) {
                int idx = tid + 256 * i;
                int r = idx >> 3, ch = idx & 7;
                CP_ASYNC16(base + r * LA_STR + ch * 16,
                           hin + (size_t)r * 512 + s * 64 + ch * 8);
            }
            CP_COMMIT();
        };

        cpa_slab(0);
        cpa_slab(1);
        cpa_slab(2);

        if (tid < 128) {
            s_m[tid] = done[t * 128 + tid] ? 0.f : 1.f;
            s_mn[tid] = (t + 1 < T_STEPS)
                            ? (done[(t + 1) * 128 + tid] ? 0.f : 1.f) : 1.f;
        }

        float acc[2][4];
#pragma unroll
        for (int pi = 0; pi < 2; pi++)
#pragma unroll
            for (int rr = 0; rr < 2; rr++)
#pragma unroll
                for (int cc = 0; cc < 2; cc++)
                    acc[pi][rr * 2 + cc] = xg[(size_t)(t * 128 + r1 + rr * 8) * 2048 +
                                              (cc + 2 * pi) * 512 + jb4 + L];

        for (int s = 0; s < 8; s++) {
            CP_WAIT2();
            __syncthreads();
            if (s < 5) cpa_slab(s + 3);
            else CP_COMMIT();
            uint32_t sbA = sbW + LS_A_OFF + (uint32_t)((s & 3) * LS_A_BUF);
#pragma unroll
            for (int kk2 = 0; kk2 < 4; kk2++) {
                int kb = kk2 * 32;
                uint32_t ah[4], bh4[4], bl4[4];
                ldsm4(sbA + arow + kb, ah);
                uint32_t bo = brow + s * 128 + kb;
                ldsm4(sbW + bo, bh4);
                ldsm4(sbW + 16 * LW_STR + bo, bl4);
#pragma unroll
                for (int pi = 0; pi < 2; pi++) {
                    float* d = acc[pi];
                    mma16816(d, ah, &bh4[pi * 2]);
                    mma16816(d, ah, &bl4[pi * 2]);
                }
            }
        }

#pragma unroll
        for (int rr = 0; rr < 2; rr++) {
            int r = r1 + rr * 8;
            float m = s_m[r];
            float mn = s_mn[r];
            int j = jb4 + L;
            float gi = acc[0][rr * 2 + 0];
            float gf = acc[0][rr * 2 + 1];
            float gg = acc[1][rr * 2 + 0];
            float go = acc[1][rr * 2 + 1];
            float cn = sigm(gf) * (creg[rr] * m) + sigm(gi) * tanhf(gg);
            float hn = sigm(go) * tanhf(cn);
            creg[rr] = cn;
            g_feat[(size_t)(t * 128 + r) * 512 + j] = __float2half(hn);
            hout[(size_t)r * 512 + j] = __float2half(hn * mn);
        }
        grid_bar();
    }
}

// ----------------------------------------------------------------------------
// Head: warp per row; actor/critic GEMV + log_softmax/entropy/prob pack.
// ----------------------------------------------------------------------------
__global__ __launch_bounds__(256) void head_kernel(
    const float* __restrict__ lf, const float* __restrict__ aw,
    const float* __restrict__ ab, const float* __restrict__ cw,
    const float* __restrict__ cb, const int* __restrict__ action,
    float* __restrict__ out) {
    int warp = (blockIdx.x * blockDim.x + threadIdx.x) >> 5;
    int lane = threadIdx.x & 31;
    if (warp >= TBTOT) return;
    float4 f = *(const float4*)(lf + (size_t)warp * FE + lane * 4);
    float r[8];
#pragma unroll
    for (int a = 0; a < 7; a++) {
        float4 w = *(const float4*)(aw + a * FE + lane * 4);
        r[a] = f.x * w.x + f.y * w.y + f.z * w.z + f.w * w.w;
    }
    {
        float4 w = *(const float4*)(cw + lane * 4);
        r[7] = f.x * w.x + f.y * w.y + f.z * w.z + f.w * w.w;
    }
#pragma unroll
    for (int a = 0; a < 8; a++)
#pragma unroll
        for (int s = 16; s > 0; s >>= 1)
            r[a] += __shfl_xor_sync(0xffffffffu, r[a], s);

    if (lane == 0) {
        float lg[7];
        float mx = -1e30f;
#pragma unroll
        for (int a = 0; a < 7; a++) {
            lg[a] = r[a] + ab[a];
            mx = fmaxf(mx, lg[a]);
        }
        float se = 0.f;
        float e[7];
#pragma unroll
        for (int a = 0; a < 7; a++) {
            e[a] = expf(lg[a] - mx);
            se += e[a];
        }
        float lse = mx + logf(se);
        float inv = 1.f / se;
        float ent = 0.f;
        float* o = out + (size_t)warp * 10;
#pragma unroll
        for (int a = 0; a < 7; a++) {
            float p = e[a] * inv;
            float lp = lg[a] - lse;
            ent -= p * lp;
            o[3 + a] = p;
        }
        int act = action[warp];
        o[0] = lg[act] - lse;
        o[1] = ent;
        o[2] = r[7] + cb[0];
    }
}

// ----------------------------------------------------------------------------
// Launch (fork-join second stream overlaps preps with conv)
// ----------------------------------------------------------------------------
extern "C" void kernel_launch(void* const* d_in, const int* in_sizes, int n_in,
                              void* d_out, int out_size) {
    const float* x    = (const float*)d_in[0];
    const int* done   = (const int*)d_in[1];
    const int* z      = (const int*)d_in[2];
    const int* action = (const int*)d_in[3];
    const float* h0   = (const float*)d_in[4];
    const float* c0   = (const float*)d_in[5];
    const float* c1w = (const float*)d_in[6];  const float* c1b = (const float*)d_in[7];
    const float* c2w = (const float*)d_in[8];  const float* c2b = (const float*)d_in[9];
    const float* c3w = (const float*)d_in[10]; const float* c3b = (const float*)d_in[11];
    const float* fc1w = (const float*)d_in[12]; const float* fc1b = (const float*)d_in[13];
    const float* fc2w = (const float*)d_in[14]; const float* fc2b = (const float*)d_in[15];
    const float* wih = (const float*)d_in[16]; const float* whh = (const float*)d_in[17];
    const float* bih = (const float*)d_in[18]; const float* bhh = (const float*)d_in[19];
    const float* lfw = (const float*)d_in[20]; const float* lfb = (const float*)d_in[21];
    const float* aw = (const float*)d_in[22];  const float* ab = (const float*)d_in[23];
    const float* cw = (const float*)d_in[24];  const float* cb = (const float*)d_in[25];
    float* out = (float*)d_out;

    float *pxg, *plf, *pcst;
    __half *pa1, *ph1, *ph2, *pfeat, *phA, *phB;
    __half *pw1h, *pw1l, *pw2h, *pw2l, *pwih_h, *pwih_l, *pwlfh, *pwlfl;
    cudaGetSymbolAddress((void**)&pa1, g_a1);
    cudaGetSymbolAddress((void**)&ph1, g_h1);
    cudaGetSymbolAddress((void**)&ph2, g_h2);
    cudaGetSymbolAddress((void**)&pxg, g_xg);
    cudaGetSymbolAddress((void**)&pfeat, g_feat);
    cudaGetSymbolAddress((void**)&plf, g_lf);
    cudaGetSymbolAddress((void**)&pcst, g_cst);
    cudaGetSymbolAddress((void**)&phA, g_hA);
    cudaGetSymbolAddress((void**)&phB, g_hB);
    cudaGetSymbolAddress((void**)&pw1h, g_wfc1_hi);
    cudaGetSymbolAddress((void**)&pw1l, g_wfc1_lo);
    cudaGetSymbolAddress((void**)&pw2h, g_wfc2_hi);
    cudaGetSymbolAddress((void**)&pw2l, g_wfc2_lo);
    cudaGetSymbolAddress((void**)&pwih_h, g_wih_hi);
    cudaGetSymbolAddress((void**)&pwih_l, g_wih_lo);
    cudaGetSymbolAddress((void**)&pwlfh, g_wlf_hi);
    cudaGetSymbolAddress((void**)&pwlfl, g_wlf_lo);

    cudaFuncSetAttribute(tgemm2<1, 1, 0>, cudaFuncAttributeMaxDynamicSharedMemorySize, TG_SMEM);
    cudaFuncSetAttribute(tgemm2<0, 0, 0>, cudaFuncAttributeMaxDynamicSharedMemorySize, TG_SMEM);
    cudaFuncSetAttribute(tgemm2<1, 0, 1>, cudaFuncAttributeMaxDynamicSharedMemorySize, TG_SMEM);
    const int SMEM_CONV = IMG_BYTES + 2 * CW_HALF;
    cudaFuncSetAttribute(conv3_mma, cudaFuncAttributeMaxDynamicSharedMemorySize, SMEM_CONV);
    cudaFuncSetAttribute(lstm_persist, cudaFuncAttributeMaxDynamicSharedMemorySize, LS_SMEM);

    static cudaStream_t s2 = nullptr;
    static cudaEvent_t evF = nullptr, evJ = nullptr;
    if (s2 == nullptr) {
        cudaStreamCreateWithFlags(&s2, cudaStreamNonBlocking);
        cudaEventCreateWithFlags(&evF, cudaEventDisableTiming);
        cudaEventCreateWithFlags(&evJ, cudaEventDisableTiming);
    }

    // conv weight prep must precede conv (stream 0)
    wcprep_all<<<(11008 + 255) / 256, 256>>>(c1w, c2w, c3w);

    // fork: remaining preps on s2, concurrent with conv
    cudaEventRecord(evF, 0);
    cudaStreamWaitEvent(s2, evF, 0);
    wprep<<<(512 * 4096 + 255) / 256, 256, 0, s2>>>(fc1w, pw1h, pw1l, 512 * 4096);
    wprep<<<(512 * 512 + 255) / 256, 256, 0, s2>>>(fc2w, pw2h, pw2l, 512 * 512);
    wprep<<<(2048 * 512 + 255) / 256, 256, 0, s2>>>(wih, pwih_h, pwih_l, 2048 * 512);
    wprep_ld<<<(128 * 512 + 255) / 256, 256, 0, s2>>>(lfw, pwlfh, pwlfl, 128, 520);
    wlstm_prep<<<(2048 * 512 + 255) / 256, 256, 0, s2>>>(whh);
    pack_hc0<<<(B_ENV * HID + 255) / 256, 256, 0, s2>>>(h0, c0, done);
    cudaEventRecord(evJ, s2);

    // conv on stream 0 (overlaps s2)
    conv3_mma<<<TBTOT, 256, SMEM_CONV>>>(x, c1b, c2b, c3b);

    // join before fc1
    cudaStreamWaitEvent(0, evJ, 0);

    tgemm2<1, 1, 0><<<dim3(4, 128), 256, TG_SMEM>>>(
        pa1, pw1h, pw1l, fc1b, nullptr,
        nullptr, ph1, nullptr, 0, nullptr, TBTOT, 512, 4096);
    tgemm2<1, 1, 0><<<dim3(4, 128), 256, TG_SMEM>>>(
        ph1, pw2h, pw2l, fc2b, nullptr,
        nullptr, ph2, nullptr, 0, nullptr, TBTOT, 512, 512);
    tgemm2<0, 0, 0><<<dim3(16, 128), 256, TG_SMEM>>>(
        ph2, pwih_h, pwih_l, bih, bhh,
        pxg, nullptr, nullptr, 0, nullptr, TBTOT, 2048, 512);

    lstm_persist<<<NB_LSTM, 256, LS_SMEM>>>(pxg, done, phA, phB, pcst);

    tgemm2<1, 0, 1><<<dim3(1, 128), 256, TG_SMEM>>>(
        pfeat, pwlfh, pwlfl, lfb, nullptr,
        plf, nullptr, lfw, 520, z, TBTOT, FE, 512);

    head_kernel<<<TBTOT / 8, 256>>>(plf, aw, ab, cw, cb, action, out);
}

// round 17
// speedup vs baseline: 2.2318x; 1.3385x over previous
#include <cuda_runtime.h>
#include <cuda_fp16.h>
#include <math.h>
#include <stdint.h>

#define T_STEPS 128
#define B_ENV   128
#define HID     512
#define TBTOT   (T_STEPS * B_ENV)
#define ZD      8
#define AD      7
#define FE      128
#define NB_LSTM 128

// ----------------------------------------------------------------------------
// Scratch (device globals; no allocation allowed)
// ----------------------------------------------------------------------------
__device__ __half g_a1[TBTOT * 4096];
__device__ __half g_h1[TBTOT * HID];
__device__ __half g_h2[TBTOT * HID];
__device__ float g_xg[TBTOT * 2048];
__device__ __half g_feat[TBTOT * HID];
__device__ float g_lf[TBTOT * FE];
__device__ float g_cst[B_ENV * HID];
__device__ __half g_hA[B_ENV * HID];
__device__ __half g_hB[B_ENV * HID];
// weights: single fp16
__device__ __half g_wl[128 * 16 * 512];
__device__ __half g_wfc1[512 * 4096];
__device__ __half g_wfc2[512 * 512];
__device__ __half g_wih[2048 * 512];
__device__ __half g_wlf[128 * 512];
__device__ __half g_cw1[25 * 256];
__device__ __half g_cw2[9 * 256];
__device__ __half g_cw3[9 * 256];
// grid barrier (R13 proven)
__device__ unsigned int g_bar_cnt;
__device__ volatile unsigned int g_bar_gen;

// ============================================================================
// Helpers
// ============================================================================
__device__ __forceinline__ uint32_t smem_to_u32(const void* smem_ptr) {
    uint32_t addr;
    asm("{ .reg .u64 tmp; cvta.to.shared.u64 tmp, %1; cvt.u32.u64 %0, tmp; }"
        : "=r"(addr) : "l"(smem_ptr));
    return addr;
}

__device__ __forceinline__ void ldsm4(uint32_t addr, uint32_t* r) {
    asm volatile("ldmatrix.sync.aligned.m8n8.x4.shared.b16 {%0,%1,%2,%3}, [%4];"
        : "=r"(r[0]), "=r"(r[1]), "=r"(r[2]), "=r"(r[3]) : "r"(addr));
}

__device__ __forceinline__ void mma16816(float* d, const uint32_t* a,
                                         const uint32_t* b) {
    asm volatile(
        "mma.sync.aligned.m16n8k16.row.col.f32.f16.f16.f32 "
        "{%0,%1,%2,%3}, {%4,%5,%6,%7}, {%8,%9}, {%0,%1,%2,%3};"
        : "+f"(d[0]), "+f"(d[1]), "+f"(d[2]), "+f"(d[3])
        : "r"(a[0]), "r"(a[1]), "r"(a[2]), "r"(a[3]), "r"(b[0]), "r"(b[1]));
}

#define CP_ASYNC16(dst, src) \
    asm volatile("cp.async.ca.shared.global [%0], [%1], 16;" \
        :: "r"(dst), "l"(src) : "memory")
#define CP_COMMIT() asm volatile("cp.async.commit_group;" ::: "memory")
#define CP_WAIT2() asm volatile("cp.async.wait_group 2;" ::: "memory")

__device__ __forceinline__ void grid_bar() {
    __threadfence();
    __syncthreads();
    if (threadIdx.x == 0) {
        unsigned int gen = g_bar_gen;
        if (atomicAdd(&g_bar_cnt, 1u) == NB_LSTM - 1) {
            g_bar_cnt = 0;
            __threadfence();
            g_bar_gen = gen + 1;
        } else {
            while (g_bar_gen == gen) { }
            __threadfence();
        }
    }
    __syncthreads();
}

// ----------------------------------------------------------------------------
// Weight prep kernels (fp16, no residual)
// ----------------------------------------------------------------------------
__global__ void wprep(const float* __restrict__ w, __half* __restrict__ o, int total) {
    int idx = blockIdx.x * blockDim.x + threadIdx.x;
    if (idx >= total) return;
    o[idx] = __float2half(w[idx]);
}

__global__ void wprep_ld(const float* __restrict__ w, __half* __restrict__ o,
                         int rows, int ldw) {
    int idx = blockIdx.x * blockDim.x + threadIdx.x;
    if (idx >= rows * 512) return;
    int row = idx >> 9;
    int k = idx & 511;
    o[(size_t)row * 512 + k] = __float2half(w[(size_t)row * ldw + k]);
}

__global__ void wcprep_all(const float* __restrict__ w1, const float* __restrict__ w2,
                           const float* __restrict__ w3) {
    int idx = blockIdx.x * blockDim.x + threadIdx.x;
    const float* w;
    __half* o;
    int taps, local;
    if (idx < 6400) { w = w1; o = g_cw1; taps = 25; local = idx; }
    else if (idx < 8704) { w = w2; o = g_cw2; taps = 9; local = idx - 6400; }
    else if (idx < 11008) { w = w3; o = g_cw3; taps = 9; local = idx - 8704; }
    else return;
    int r = local & 255;
    int t = local >> 8;
    o[t * 256 + r] = __float2half(w[r * taps + t]);
}

__global__ void wlstm_prep(const float* __restrict__ whh) {
    int idx = blockIdx.x * blockDim.x + threadIdx.x;
    if (idx >= 2048 * 512) return;
    int row = idx >> 9;
    int k = idx & 511;
    int g = row >> 9, j = row & 511;
    int blk = j >> 2, jj = j & 3;
    int n = 2 * jj + (g & 1) + 8 * (g >> 1);
    g_wl[((size_t)(blk * 16 + n)) * 512 + k] = __float2half(whh[(size_t)row * 512 + k]);
}

__global__ void pack_hc0(const float* __restrict__ h0, const float* __restrict__ c0,
                         const int* __restrict__ done) {
    int i = blockIdx.x * blockDim.x + threadIdx.x;
    if (i >= B_ENV * HID) return;
    int b = i >> 9;
    float m = done[b] ? 0.f : 1.f;
    g_hA[i] = __float2half(h0[i] * m);
    g_cst[i] = c0[i];
}

// ----------------------------------------------------------------------------
// tgemm2 fp16 single: A fp16, W fp16. cp.async depth-3, 4 buffers.
// ----------------------------------------------------------------------------
#define SMSTR 80
#define TG_BUF 20480    // per-stage: A | W, each 10240
#define TG_SMEM (4 * TG_BUF)

template <int ACT, int OUTHALF, int ZMODE>
__global__ __launch_bounds__(256) void tgemm2(
    const __half* __restrict__ A, const __half* __restrict__ W,
    const float* __restrict__ bias, const float* __restrict__ bias2,
    float* __restrict__ C, __half* __restrict__ Ch,
    const float* __restrict__ Wzf, int ldw, const int* __restrict__ z,
    int M, int N, int K) {
    extern __shared__ uint8_t sm[];
    uint32_t sb = smem_to_u32(sm);
    int tid = threadIdx.x;
    int lane = tid & 31;
    int wid = tid >> 5;
    int wm = wid & 3, wn = wid >> 2;
    int m0 = blockIdx.y * 128, n0 = blockIdx.x * 128;
    int sr0 = tid >> 2, sq = tid & 3;
    int nslab = K / 32;

    float acc[2][8][4];
#pragma unroll
    for (int i = 0; i < 2; i++)
#pragma unroll
        for (int j = 0; j < 8; j++)
#pragma unroll
            for (int q = 0; q < 4; q++) acc[i][j][q] = 0.f;

    auto cpa = [&](int s) {
        uint32_t buf = sb + (uint32_t)((s & 3) * TG_BUF);
        size_t ko = (size_t)s * 32 + sq * 8;
#pragma unroll
        for (int q = 0; q < 2; q++) {
            int r = sr0 + 64 * q;
            uint32_t d = (uint32_t)(r * SMSTR + sq * 16);
            CP_ASYNC16(buf + d,         A + (size_t)(m0 + r) * K + ko);
            CP_ASYNC16(buf + 10240 + d, W + (size_t)(n0 + r) * K + ko);
        }
        CP_COMMIT();
    };

    cpa(0); cpa(1); cpa(2);

    int g = lane >> 3;
    int arow_off = (lane & 7) + (g & 1) * 8;
    int akb_off = (g >> 1) * 16;
    int brow_off = (lane & 7) + (g >> 1) * 8;
    int bkb_off = (g & 1) * 16;

    for (int s = 0; s < nslab; s++) {
        CP_WAIT2();
        __syncthreads();
        if (s + 3 < nslab) cpa(s + 3);
        else CP_COMMIT();
        uint32_t buf = sb + (uint32_t)((s & 3) * TG_BUF);
#pragma unroll
        for (int kk2 = 0; kk2 < 2; kk2++) {
            int kb = kk2 * 32;
            uint32_t ah[2][4], bh[4][4];
#pragma unroll
            for (int mi = 0; mi < 2; mi++) {
                uint32_t r = (uint32_t)((wm * 32 + mi * 16 + arow_off) * SMSTR +
                                        kb + akb_off);
                ldsm4(buf + r, ah[mi]);
            }
#pragma unroll
            for (int pi = 0; pi < 4; pi++) {
                uint32_t r = (uint32_t)((wn * 64 + pi * 16 + brow_off) * SMSTR +
                                        kb + bkb_off);
                ldsm4(buf + 10240 + r, bh[pi]);
            }
#pragma unroll
            for (int mi = 0; mi < 2; mi++)
#pragma unroll
                for (int pi = 0; pi < 4; pi++)
#pragma unroll
                    for (int half = 0; half < 2; half++)
                        mma16816(acc[mi][pi * 2 + half], ah[mi], &bh[pi][half * 2]);
        }
    }
    __syncthreads();

    float* ct = (float*)sm;
#pragma unroll
    for (int mi = 0; mi < 2; mi++) {
        int r0 = wm * 32 + mi * 16 + (lane >> 2);
        int z0 = 0, z1 = 0;
        if (ZMODE) {
            z0 = z[m0 + r0];
            z1 = z[m0 + r0 + 8];
        }
#pragma unroll
        for (int ni = 0; ni < 8; ni++) {
            int c = wn * 64 + ni * 8 + (lane & 3) * 2;
            float b0 = bias[n0 + c], b1 = bias[n0 + c + 1];
            if (bias2) { b0 += bias2[n0 + c]; b1 += bias2[n0 + c + 1]; }
            float v0 = acc[mi][ni][0] + b0;
            float v1 = acc[mi][ni][1] + b1;
            float v2 = acc[mi][ni][2] + b0;
            float v3 = acc[mi][ni][3] + b1;
            if (ZMODE) {
                v0 += Wzf[(size_t)(n0 + c) * ldw + 512 + z0];
                v1 += Wzf[(size_t)(n0 + c + 1) * ldw + 512 + z0];
                v2 += Wzf[(size_t)(n0 + c) * ldw + 512 + z1];
                v3 += Wzf[(size_t)(n0 + c + 1) * ldw + 512 + z1];
            }
            if (ACT) {
                v0 = v0 > 0.f ? v0 : 0.01f * v0;
                v1 = v1 > 0.f ? v1 : 0.01f * v1;
                v2 = v2 > 0.f ? v2 : 0.01f * v2;
                v3 = v3 > 0.f ? v3 : 0.01f * v3;
            }
            ct[r0 * 132 + c] = v0;
            ct[r0 * 132 + c + 1] = v1;
            ct[(r0 + 8) * 132 + c] = v2;
            ct[(r0 + 8) * 132 + c + 1] = v3;
        }
    }
    __syncthreads();
    {
        int r8 = tid >> 5;
        int c4 = (tid & 31) * 4;
#pragma unroll
        for (int p = 0; p < 16; p++) {
            int r = p * 8 + r8;
            float4 v = *(const float4*)(ct + r * 132 + c4);
            size_t o = (size_t)(m0 + r) * N + n0 + c4;
            if (OUTHALF) {
                *(__half2*)(Ch + o) = __floats2half2_rn(v.x, v.y);
                *(__half2*)(Ch + o + 2) = __floats2half2_rn(v.z, v.w);
            } else {
                *(float4*)(C + o) = v;
            }
        }
    }
}

// ----------------------------------------------------------------------------
// HMMA conv fp16 single: 1 MMA per (tap, mi, nh)
// ----------------------------------------------------------------------------
#define PSTR 48
#define IMG_BYTES (400 * PSTR)      // 19200
#define CW_OFF   IMG_BYTES
#define CW_SZ    12800              // 25 taps * 512B max

template <int KS, int P, int LAST>
__device__ __forceinline__ void conv_hmma_layer(
    uint8_t* csm, uint32_t sbase, const __half* wsrc,
    const float* __restrict__ bias,
    __half* go, int tid, int lane, int wid) {
    const int taps = KS * KS;
    {
        const uint4* sh = (const uint4*)wsrc;
        uint4* dh = (uint4*)(csm + CW_OFF);
        for (int i = tid; i < taps * 32; i += 256) dh[i] = sh[i];
    }
    __syncthreads();

    float acc[2][2][4];
#pragma unroll
    for (int a = 0; a < 2; a++)
#pragma unroll
        for (int b = 0; b < 2; b++)
#pragma unroll
            for (int q = 0; q < 4; q++) acc[a][b][q] = 0.f;

    int g = lane >> 3;
    int h0 = wid * 2;
    uint32_t aoff[2];
#pragma unroll
    for (int mi = 0; mi < 2; mi++)
        aoff[mi] = (uint32_t)(((h0 + mi + 2) * 20 + 2 + (lane & 7) + (g & 1) * 8) * PSTR +
                              (g >> 1) * 16);
    uint32_t boff = (uint32_t)(((lane & 7) + (g >> 1) * 8) * 32 + (g & 1) * 16);
    uint32_t wb = sbase + CW_OFF;

#pragma unroll
    for (int kh = 0; kh < KS; kh++) {
#pragma unroll
        for (int kw = 0; kw < KS; kw++) {
            int t = kh * KS + kw;
            int shift = ((kh - P) * 20 + (kw - P)) * PSTR;
            uint32_t bh4[4];
            ldsm4(wb + t * 512 + boff, bh4);
#pragma unroll
            for (int mi = 0; mi < 2; mi++) {
                uint32_t ah[4];
                ldsm4(sbase + aoff[mi] + shift, ah);
#pragma unroll
                for (int nh = 0; nh < 2; nh++)
                    mma16816(acc[mi][nh], ah, &bh4[nh * 2]);
            }
        }
    }
    __syncthreads();

#pragma unroll
    for (int mi = 0; mi < 2; mi++) {
        int h = h0 + mi;
#pragma unroll
        for (int nh = 0; nh < 2; nh++) {
            int co = nh * 8 + (lane & 3) * 2;
            float b0 = bias[co], b1 = bias[co + 1];
#pragma unroll
            for (int rr = 0; rr < 2; rr++) {
                int w = (lane >> 2) + rr * 8;
                float v0 = acc[mi][nh][rr * 2 + 0] + b0;
                float v1 = acc[mi][nh][rr * 2 + 1] + b1;
                v0 = v0 > 0.f ? v0 : 0.01f * v0;
                v1 = v1 > 0.f ? v1 : 0.01f * v1;
                if (LAST) {
                    int k0 = co * 256 + h * 16 + w;
                    go[k0] = __float2half(v0);
                    go[k0 + 256] = __float2half(v1);
                } else {
                    int pb = ((h + 2) * 20 + (w + 2)) * PSTR + co * 2;
                    *(__half2*)(csm + pb) = __floats2half2_rn(v0, v1);
                }
            }
        }
    }
    __syncthreads();
}

__global__ __launch_bounds__(256) void conv3_mma(
    const float* __restrict__ x,
    const float* __restrict__ b1, const float* __restrict__ b2,
    const float* __restrict__ b3) {
    extern __shared__ uint8_t csm[];
    uint32_t sbase = smem_to_u32(csm);
    int tid = threadIdx.x;
    int lane = tid & 31;
    int wid = tid >> 5;
    int img = blockIdx.x;
    const float* xi = x + (size_t)img * 4096;

    for (int i = tid; i < IMG_BYTES / 4; i += 256)
        ((uint32_t*)csm)[i] = 0;
    __syncthreads();
    for (int i = tid; i < 4096; i += 256) {
        int ci = i >> 8, p = i & 255;
        int h = p >> 4, w = p & 15;
        int pb = ((h + 2) * 20 + (w + 2)) * PSTR + ci * 2;
        *(__half*)(csm + pb) = __float2half(xi[i]);
    }
    __syncthreads();

    __half* go = g_a1 + (size_t)img * 4096;
    conv_hmma_layer<5, 2, 0>(csm, sbase, g_cw1, b1, go, tid, lane, wid);
    conv_hmma_layer<3, 1, 0>(csm, sbase, g_cw2, b2, go, tid, lane, wid);
    conv_hmma_layer<3, 1, 1>(csm, sbase, g_cw3, b3, go, tid, lane, wid);
}

// ----------------------------------------------------------------------------
// Persistent LSTM fp16 single: W resident (17KB), 64-k slabs, depth-3.
// ----------------------------------------------------------------------------
__device__ __forceinline__ float sigm(float x) { return 1.f / (1.f + expf(-x)); }

#define LW_STR   1040
#define LA_STR   144
#define LS_W_SZ  (16 * LW_STR)                     // 16640
#define LS_A_OFF LS_W_SZ
#define LS_A_BUF (128 * LA_STR)                    // 18432
#define LS_M_OFF (LS_A_OFF + 4 * LS_A_BUF)         // 90368
#define LS_SMEM  (LS_M_OFF + 1024)                 // 91392

__global__ __launch_bounds__(256) void lstm_persist(
    const float* __restrict__ xg, const int* __restrict__ done,
    __half* __restrict__ hA, __half* __restrict__ hB,
    float* __restrict__ c_st) {
    extern __shared__ uint8_t psm[];
    float* s_m  = (float*)(psm + LS_M_OFF);
    float* s_mn = (float*)(psm + LS_M_OFF + 512);
    uint32_t sbW = smem_to_u32(psm);
    int tid = threadIdx.x, lane = tid & 31, wid = tid >> 5;
    int blk = blockIdx.x;
    int jb4 = blk * 4;

    {
        const uint4* Wg = (const uint4*)(g_wl + (size_t)blk * 16 * 512);
#pragma unroll
        for (int i = 0; i < 4; i++) {
            int i4 = tid + 256 * i;
            int r = i4 >> 6, q = i4 & 63;
            *(uint4*)(psm + r * LW_STR + q * 16) = Wg[i4];
        }
    }

    int r1 = wid * 16 + (lane >> 2);
    int L = lane & 3;
    int gq = lane >> 3;
    uint32_t arow = (uint32_t)((wid * 16 + (lane & 7) + (gq & 1) * 8) * LA_STR +
                               (gq >> 1) * 16);
    uint32_t brow = (uint32_t)(((lane & 7) + (gq >> 1) * 8) * LW_STR + (gq & 1) * 16);

    float creg[2];
#pragma unroll
    for (int rr = 0; rr < 2; rr++)
        creg[rr] = c_st[(size_t)(r1 + rr * 8) * 512 + jb4 + L];
    __syncthreads();

    for (int t = 0; t < T_STEPS; t++) {
        const __half* hin = (t & 1) ? hB : hA;
        __half* hout = (t & 1) ? hA : hB;

        auto cpa_slab = [&](int s) {
            uint32_t base = sbW + LS_A_OFF + (uint32_t)((s & 3) * LS_A_BUF);
#pragma unroll
            for (int i = 0; i < 4; i++) {
                int idx = tid + 256 * i;
                int r = idx >> 3, ch = idx & 7;
                CP_ASYNC16(base + r * LA_STR + ch * 16,
                           hin + (size_t)r * 512 + s * 64 + ch * 8);
            }
            CP_COMMIT();
        };

        cpa_slab(0);
        cpa_slab(1);
        cpa_slab(2);

        if (tid < 128) {
            s_m[tid] = done[t * 128 + tid] ? 0.f : 1.f;
            s_mn[tid] = (t + 1 < T_STEPS)
                            ? (done[(t + 1) * 128 + tid] ? 0.f : 1.f) : 1.f;
        }

        float acc[2][4];
#pragma unroll
        for (int pi = 0; pi < 2; pi++)
#pragma unroll
            for (int rr = 0; rr < 2; rr++)
#pragma unroll
                for (int cc = 0; cc < 2; cc++)
                    acc[pi][rr * 2 + cc] = xg[(size_t)(t * 128 + r1 + rr * 8) * 2048 +
                                              (cc + 2 * pi) * 512 + jb4 + L];

        for (int s = 0; s < 8; s++) {
            CP_WAIT2();
            __syncthreads();
            if (s < 5) cpa_slab(s + 3);
            else CP_COMMIT();
            uint32_t sbA = sbW + LS_A_OFF + (uint32_t)((s & 3) * LS_A_BUF);
#pragma unroll
            for (int kk2 = 0; kk2 < 4; kk2++) {
                int kb = kk2 * 32;
                uint32_t ah[4], bh4[4];
                ldsm4(sbA + arow + kb, ah);
                ldsm4(sbW + brow + s * 128 + kb, bh4);
#pragma unroll
                for (int pi = 0; pi < 2; pi++)
                    mma16816(acc[pi], ah, &bh4[pi * 2]);
            }
        }

#pragma unroll
        for (int rr = 0; rr < 2; rr++) {
            int r = r1 + rr * 8;
            float m = s_m[r];
            float mn = s_mn[r];
            int j = jb4 + L;
            float gi = acc[0][rr * 2 + 0];
            float gf = acc[0][rr * 2 + 1];
            float gg = acc[1][rr * 2 + 0];
            float go = acc[1][rr * 2 + 1];
            float cn = sigm(gf) * (creg[rr] * m) + sigm(gi) * tanhf(gg);
            float hn = sigm(go) * tanhf(cn);
            creg[rr] = cn;
            g_feat[(size_t)(t * 128 + r) * 512 + j] = __float2half(hn);
            hout[(size_t)r * 512 + j] = __float2half(hn * mn);
        }
        grid_bar();
    }
}

// ----------------------------------------------------------------------------
// Head: warp per row; actor/critic GEMV + log_softmax/entropy/prob pack.
// ----------------------------------------------------------------------------
__global__ __launch_bounds__(256) void head_kernel(
    const float* __restrict__ lf, const float* __restrict__ aw,
    const float* __restrict__ ab, const float* __restrict__ cw,
    const float* __restrict__ cb, const int* __restrict__ action,
    float* __restrict__ out) {
    int warp = (blockIdx.x * blockDim.x + threadIdx.x) >> 5;
    int lane = threadIdx.x & 31;
    if (warp >= TBTOT) return;
    float4 f = *(const float4*)(lf + (size_t)warp * FE + lane * 4);
    float r[8];
#pragma unroll
    for (int a = 0; a < 7; a++) {
        float4 w = *(const float4*)(aw + a * FE + lane * 4);
        r[a] = f.x * w.x + f.y * w.y + f.z * w.z + f.w * w.w;
    }
    {
        float4 w = *(const float4*)(cw + lane * 4);
        r[7] = f.x * w.x + f.y * w.y + f.z * w.z + f.w * w.w;
    }
#pragma unroll
    for (int a = 0; a < 8; a++)
#pragma unroll
        for (int s = 16; s > 0; s >>= 1)
            r[a] += __shfl_xor_sync(0xffffffffu, r[a], s);

    if (lane == 0) {
        float lg[7];
        float mx = -1e30f;
#pragma unroll
        for (int a = 0; a < 7; a++) {
            lg[a] = r[a] + ab[a];
            mx = fmaxf(mx, lg[a]);
        }
        float se = 0.f;
        float e[7];
#pragma unroll
        for (int a = 0; a < 7; a++) {
            e[a] = expf(lg[a] - mx);
            se += e[a];
        }
        float lse = mx + logf(se);
        float inv = 1.f / se;
        float ent = 0.f;
        float* o = out + (size_t)warp * 10;
#pragma unroll
        for (int a = 0; a < 7; a++) {
            float p = e[a] * inv;
            float lp = lg[a] - lse;
            ent -= p * lp;
            o[3 + a] = p;
        }
        int act = action[warp];
        o[0] = lg[act] - lse;
        o[1] = ent;
        o[2] = r[7] + cb[0];
    }
}

// ----------------------------------------------------------------------------
// Launch (fork-join second stream overlaps preps with conv)
// ----------------------------------------------------------------------------
extern "C" void kernel_launch(void* const* d_in, const int* in_sizes, int n_in,
                              void* d_out, int out_size) {
    const float* x    = (const float*)d_in[0];
    const int* done   = (const int*)d_in[1];
    const int* z      = (const int*)d_in[2];
    const int* action = (const int*)d_in[3];
    const float* h0   = (const float*)d_in[4];
    const float* c0   = (const float*)d_in[5];
    const float* c1w = (const float*)d_in[6];  const float* c1b = (const float*)d_in[7];
    const float* c2w = (const float*)d_in[8];  const float* c2b = (const float*)d_in[9];
    const float* c3w = (const float*)d_in[10]; const float* c3b = (const float*)d_in[11];
    const float* fc1w = (const float*)d_in[12]; const float* fc1b = (const float*)d_in[13];
    const float* fc2w = (const float*)d_in[14]; const float* fc2b = (const float*)d_in[15];
    const float* wih = (const float*)d_in[16]; const float* whh = (const float*)d_in[17];
    const float* bih = (const float*)d_in[18]; const float* bhh = (const float*)d_in[19];
    const float* lfw = (const float*)d_in[20]; const float* lfb = (const float*)d_in[21];
    const float* aw = (const float*)d_in[22];  const float* ab = (const float*)d_in[23];
    const float* cw = (const float*)d_in[24];  const float* cb = (const float*)d_in[25];
    float* out = (float*)d_out;

    float *pxg, *plf, *pcst;
    __half *pa1, *ph1, *ph2, *pfeat, *phA, *phB;
    __half *pw1, *pw2, *pwih, *pwlf;
    cudaGetSymbolAddress((void**)&pa1, g_a1);
    cudaGetSymbolAddress((void**)&ph1, g_h1);
    cudaGetSymbolAddress((void**)&ph2, g_h2);
    cudaGetSymbolAddress((void**)&pxg, g_xg);
    cudaGetSymbolAddress((void**)&pfeat, g_feat);
    cudaGetSymbolAddress((void**)&plf, g_lf);
    cudaGetSymbolAddress((void**)&pcst, g_cst);
    cudaGetSymbolAddress((void**)&phA, g_hA);
    cudaGetSymbolAddress((void**)&phB, g_hB);
    cudaGetSymbolAddress((void**)&pw1, g_wfc1);
    cudaGetSymbolAddress((void**)&pw2, g_wfc2);
    cudaGetSymbolAddress((void**)&pwih, g_wih);
    cudaGetSymbolAddress((void**)&pwlf, g_wlf);

    cudaFuncSetAttribute(tgemm2<1, 1, 0>, cudaFuncAttributeMaxDynamicSharedMemorySize, TG_SMEM);
    cudaFuncSetAttribute(tgemm2<0, 0, 0>, cudaFuncAttributeMaxDynamicSharedMemorySize, TG_SMEM);
    cudaFuncSetAttribute(tgemm2<1, 0, 1>, cudaFuncAttributeMaxDynamicSharedMemorySize, TG_SMEM);
    const int SMEM_CONV = IMG_BYTES + CW_SZ;
    cudaFuncSetAttribute(conv3_mma, cudaFuncAttributeMaxDynamicSharedMemorySize, SMEM_CONV);
    cudaFuncSetAttribute(lstm_persist, cudaFuncAttributeMaxDynamicSharedMemorySize, LS_SMEM);

    static cudaStream_t s2 = nullptr;
    static cudaEvent_t evF = nullptr, evJ = nullptr;
    if (s2 == nullptr) {
        cudaStreamCreateWithFlags(&s2, cudaStreamNonBlocking);
        cudaEventCreateWithFlags(&evF, cudaEventDisableTiming);
        cudaEventCreateWithFlags(&evJ, cudaEventDisableTiming);
    }

    // conv weight prep must precede conv (stream 0)
    wcprep_all<<<(11008 + 255) / 256, 256>>>(c1w, c2w, c3w);

    // fork: remaining preps on s2, concurrent with conv
    cudaEventRecord(evF, 0);
    cudaStreamWaitEvent(s2, evF, 0);
    wprep<<<(512 * 4096 + 255) / 256, 256, 0, s2>>>(fc1w, pw1, 512 * 4096);
    wprep<<<(512 * 512 + 255) / 256, 256, 0, s2>>>(fc2w, pw2, 512 * 512);
    wprep<<<(2048 * 512 + 255) / 256, 256, 0, s2>>>(wih, pwih, 2048 * 512);
    wprep_ld<<<(128 * 512 + 255) / 256, 256, 0, s2>>>(lfw, pwlf, 128, 520);
    wlstm_prep<<<(2048 * 512 + 255) / 256, 256, 0, s2>>>(whh);
    pack_hc0<<<(B_ENV * HID + 255) / 256, 256, 0, s2>>>(h0, c0, done);
    cudaEventRecord(evJ, s2);

    // conv on stream 0 (overlaps s2)
    conv3_mma<<<TBTOT, 256, SMEM_CONV>>>(x, c1b, c2b, c3b);

    // join before fc1
    cudaStreamWaitEvent(0, evJ, 0);

    tgemm2<1, 1, 0><<<dim3(4, 128), 256, TG_SMEM>>>(
        pa1, pw1, fc1b, nullptr,
        nullptr, ph1, nullptr, 0, nullptr, TBTOT, 512, 4096);
    tgemm2<1, 1, 0><<<dim3(4, 128), 256, TG_SMEM>>>(
        ph1, pw2, fc2b, nullptr,
        nullptr, ph2, nullptr, 0, nullptr, TBTOT, 512, 512);
    tgemm2<0, 0, 0><<<dim3(16, 128), 256, TG_SMEM>>>(
        ph2, pwih, bih, bhh,
        pxg, nullptr, nullptr, 0, nullptr, TBTOT, 2048, 512);

    lstm_persist<<<NB_LSTM, 256, LS_SMEM>>>(pxg, done, phA, phB, pcst);

    tgemm2<1, 0, 1><<<dim3(1, 128), 256, TG_SMEM>>>(
        pfeat, pwlf, lfb, nullptr,
        plf, nullptr, lfw, 520, z, TBTOT, FE, 512);

    head_kernel<<<TBTOT / 8, 256>>>(plf, aw, ab, cw, cb, action, out);
}